// round 1
// baseline (speedup 1.0000x reference)
#include <cuda_runtime.h>
#include <cuda_bf16.h>

// Problem constants (from reference): B=4, L=2048, D_MODEL=1024, H=16, Dh=Dv=64
#define BB 4
#define LL 2048
#define DM 1024
#define HH 16
#define DH 64
#define MROWS (BB * LL)   // 8192

// Scratch (allocation-free rule: __device__ globals)
__device__ float g_Q[MROWS * DM];
__device__ float g_K[MROWS * DM];
__device__ float g_V[MROWS * DM];
__device__ float g_ctx[MROWS * DM];

// ---------------------------------------------------------------------------
// SGEMM: C[m,n] = sum_k A[m,k] * W[n,k]   (A: M x 1024 row-major, W: 1024 x 1024
// row-major "torch Linear" layout, C: M x 1024). BM=BN=128, BK=8, 8x8 micro.
// grid: (1024/128, M/128 [, z]) block: 256
// ---------------------------------------------------------------------------
__device__ __forceinline__ void gemm_body_1024(const float* __restrict__ A,
                                               const float* __restrict__ W,
                                               float* __restrict__ C) {
    __shared__ float As[8][128];
    __shared__ float Bs[8][128];

    const int tid = threadIdx.x;
    const int tx = tid & 15;        // 0..15 -> col micro
    const int ty = tid >> 4;        // 0..15 -> row micro
    const int row0 = blockIdx.y * 128;
    const int col0 = blockIdx.x * 128;

    const int lr = tid >> 1;        // 0..127 load row
    const int lc = (tid & 1) * 4;   // 0 or 4 load col (float4)

    const float* Ap = A + (size_t)(row0 + lr) * DM + lc;
    const float* Wp = W + (size_t)(col0 + lr) * DM + lc;

    float acc[8][8];
#pragma unroll
    for (int i = 0; i < 8; ++i)
#pragma unroll
        for (int j = 0; j < 8; ++j) acc[i][j] = 0.0f;

    for (int kk = 0; kk < DM; kk += 8) {
        float4 a4 = *(const float4*)(Ap + kk);
        float4 b4 = *(const float4*)(Wp + kk);
        As[lc + 0][lr] = a4.x; As[lc + 1][lr] = a4.y;
        As[lc + 2][lr] = a4.z; As[lc + 3][lr] = a4.w;
        Bs[lc + 0][lr] = b4.x; Bs[lc + 1][lr] = b4.y;
        Bs[lc + 2][lr] = b4.z; Bs[lc + 3][lr] = b4.w;
        __syncthreads();

#pragma unroll
        for (int k = 0; k < 8; ++k) {
            float ar[8], br[8];
#pragma unroll
            for (int i = 0; i < 8; ++i) ar[i] = As[k][ty * 8 + i];
#pragma unroll
            for (int j = 0; j < 8; ++j) br[j] = Bs[k][tx * 8 + j];
#pragma unroll
            for (int i = 0; i < 8; ++i)
#pragma unroll
                for (int j = 0; j < 8; ++j)
                    acc[i][j] = fmaf(ar[i], br[j], acc[i][j]);
        }
        __syncthreads();
    }

#pragma unroll
    for (int i = 0; i < 8; ++i) {
        float* cp = C + (size_t)(row0 + ty * 8 + i) * DM + col0 + tx * 8;
        *(float4*)(cp)     = make_float4(acc[i][0], acc[i][1], acc[i][2], acc[i][3]);
        *(float4*)(cp + 4) = make_float4(acc[i][4], acc[i][5], acc[i][6], acc[i][7]);
    }
}

__global__ void __launch_bounds__(256)
qkv_gemm(const float* __restrict__ x, const float* __restrict__ Wq,
         const float* __restrict__ Wk, const float* __restrict__ Wv) {
    const float* W = (blockIdx.z == 0) ? Wq : (blockIdx.z == 1) ? Wk : Wv;
    float* C = (blockIdx.z == 0) ? g_Q : (blockIdx.z == 1) ? g_K : g_V;
    gemm_body_1024(x, W, C);
}

__global__ void __launch_bounds__(256)
out_gemm(const float* __restrict__ Wo, float* __restrict__ out) {
    gemm_body_1024(g_ctx, Wo, out);
}

// ---------------------------------------------------------------------------
// Flash attention, fp32 SIMT. Br=Bc=64, Dh=64. 64 threads (8x8 grid), each
// thread owns an 8x8 S/P tile and an 8x8 O tile. Online softmax; row
// reductions via shfl_xor over the 8 lanes that share a row group.
// grid: (L/64, B*H); block: 64; dynamic smem = 4 * 64*65 floats
// ---------------------------------------------------------------------------
#define PADW 65

__global__ void __launch_bounds__(64)
flash_attn(const unsigned char* __restrict__ mask) {
    extern __shared__ float sm[];
    float* Qs = sm;                 // [64][65]
    float* Ks = sm + 64 * PADW;     // [64][65]
    float* Vs = sm + 2 * 64 * PADW; // [64][65]
    float* Ps = sm + 3 * 64 * PADW; // [64][65]
    __shared__ unsigned char msk[64];

    const int tid = threadIdx.x;    // 0..63
    const int tx = tid & 7;         // col group
    const int ty = tid >> 3;        // row group
    const int bh = blockIdx.y;
    const int b = bh >> 4;
    const int h = bh & 15;
    const int q0 = blockIdx.x * 64;
    const size_t headoff = (size_t)b * LL * DM + (size_t)h * DH;

    // Load Q tile: one row per thread, 64 contiguous floats
    {
        const float* qr = g_Q + headoff + (size_t)(q0 + tid) * DM;
#pragma unroll
        for (int c = 0; c < 64; c += 4) {
            float4 v = *(const float4*)(qr + c);
            Qs[tid * PADW + c + 0] = v.x;
            Qs[tid * PADW + c + 1] = v.y;
            Qs[tid * PADW + c + 2] = v.z;
            Qs[tid * PADW + c + 3] = v.w;
        }
    }

    float m_i[8], l_i[8], o[8][8];
#pragma unroll
    for (int i = 0; i < 8; ++i) {
        m_i[i] = -1e30f;
        l_i[i] = 0.0f;
#pragma unroll
        for (int c = 0; c < 8; ++c) o[i][c] = 0.0f;
    }

    for (int kv0 = 0; kv0 < LL; kv0 += 64) {
        // Load K, V tiles (one row per thread) + mask bytes
        {
            const float* kr = g_K + headoff + (size_t)(kv0 + tid) * DM;
            const float* vr = g_V + headoff + (size_t)(kv0 + tid) * DM;
#pragma unroll
            for (int c = 0; c < 64; c += 4) {
                float4 kv4 = *(const float4*)(kr + c);
                Ks[tid * PADW + c + 0] = kv4.x;
                Ks[tid * PADW + c + 1] = kv4.y;
                Ks[tid * PADW + c + 2] = kv4.z;
                Ks[tid * PADW + c + 3] = kv4.w;
                float4 vv4 = *(const float4*)(vr + c);
                Vs[tid * PADW + c + 0] = vv4.x;
                Vs[tid * PADW + c + 1] = vv4.y;
                Vs[tid * PADW + c + 2] = vv4.z;
                Vs[tid * PADW + c + 3] = vv4.w;
            }
            msk[tid] = mask[(size_t)b * LL + kv0 + tid];
        }
        __syncthreads();

        // S = Q * K^T (8x8 per thread)
        float s[8][8];
#pragma unroll
        for (int i = 0; i < 8; ++i)
#pragma unroll
            for (int j = 0; j < 8; ++j) s[i][j] = 0.0f;

#pragma unroll 8
        for (int k = 0; k < 64; ++k) {
            float aq[8], bk[8];
#pragma unroll
            for (int i = 0; i < 8; ++i) aq[i] = Qs[(ty * 8 + i) * PADW + k];
#pragma unroll
            for (int j = 0; j < 8; ++j) bk[j] = Ks[(tx * 8 + j) * PADW + k];
#pragma unroll
            for (int i = 0; i < 8; ++i)
#pragma unroll
                for (int j = 0; j < 8; ++j)
                    s[i][j] = fmaf(aq[i], bk[j], s[i][j]);
        }

        // scale (1/sqrt(64)) + mask
#pragma unroll
        for (int j = 0; j < 8; ++j) {
            const bool mj = (msk[tx * 8 + j] != 0);
#pragma unroll
            for (int i = 0; i < 8; ++i)
                s[i][j] = mj ? -1e30f : s[i][j] * 0.125f;
        }

        // online softmax update + stage P into smem
#pragma unroll
        for (int i = 0; i < 8; ++i) {
            float mt = s[i][0];
#pragma unroll
            for (int j = 1; j < 8; ++j) mt = fmaxf(mt, s[i][j]);
            mt = fmaxf(mt, __shfl_xor_sync(0xffffffffu, mt, 1, 8));
            mt = fmaxf(mt, __shfl_xor_sync(0xffffffffu, mt, 2, 8));
            mt = fmaxf(mt, __shfl_xor_sync(0xffffffffu, mt, 4, 8));
            const float mn = fmaxf(m_i[i], mt);
            const float corr = __expf(m_i[i] - mn);
            m_i[i] = mn;
            float rs = 0.0f;
#pragma unroll
            for (int j = 0; j < 8; ++j) {
                const float p = __expf(s[i][j] - mn);
                s[i][j] = p;
                rs += p;
            }
            rs += __shfl_xor_sync(0xffffffffu, rs, 1, 8);
            rs += __shfl_xor_sync(0xffffffffu, rs, 2, 8);
            rs += __shfl_xor_sync(0xffffffffu, rs, 4, 8);
            l_i[i] = l_i[i] * corr + rs;
#pragma unroll
            for (int c = 0; c < 8; ++c) o[i][c] *= corr;
#pragma unroll
            for (int j = 0; j < 8; ++j)
                Ps[(ty * 8 + i) * PADW + tx * 8 + j] = s[i][j];
        }
        __syncthreads();

        // O += P * V  (8x8 per thread; cols of O are d-dims tx*8..tx*8+7)
#pragma unroll 8
        for (int j = 0; j < 64; ++j) {
            float pj[8], vj[8];
#pragma unroll
            for (int i = 0; i < 8; ++i) pj[i] = Ps[(ty * 8 + i) * PADW + j];
#pragma unroll
            for (int c = 0; c < 8; ++c) vj[c] = Vs[j * PADW + tx * 8 + c];
#pragma unroll
            for (int i = 0; i < 8; ++i)
#pragma unroll
                for (int c = 0; c < 8; ++c)
                    o[i][c] = fmaf(pj[i], vj[c], o[i][c]);
        }
        __syncthreads();
    }

    // epilogue: normalize and write ctx in (B, L, H*Dv) layout
#pragma unroll
    for (int i = 0; i < 8; ++i) {
        const float inv = 1.0f / l_i[i];
        float* op = g_ctx + headoff + (size_t)(q0 + ty * 8 + i) * DM + tx * 8;
        *(float4*)(op)     = make_float4(o[i][0] * inv, o[i][1] * inv,
                                         o[i][2] * inv, o[i][3] * inv);
        *(float4*)(op + 4) = make_float4(o[i][4] * inv, o[i][5] * inv,
                                         o[i][6] * inv, o[i][7] * inv);
    }
}

// ---------------------------------------------------------------------------
// Launch
// ---------------------------------------------------------------------------
extern "C" void kernel_launch(void* const* d_in, const int* in_sizes, int n_in,
                              void* d_out, int out_size) {
    const float* x          = (const float*)d_in[0];
    const unsigned char* mk = (const unsigned char*)d_in[1];  // all-False in this problem
    const float* Wq         = (const float*)d_in[2];
    const float* Wk         = (const float*)d_in[3];
    const float* Wv         = (const float*)d_in[4];
    const float* Wo         = (const float*)d_in[5];
    float* out              = (float*)d_out;

    const int smem_flash = 4 * 64 * PADW * (int)sizeof(float);  // 66560 B
    cudaFuncSetAttribute(flash_attn, cudaFuncAttributeMaxDynamicSharedMemorySize,
                         smem_flash);

    dim3 gq(DM / 128, MROWS / 128, 3);   // (8, 64, 3)
    qkv_gemm<<<gq, 256>>>(x, Wq, Wk, Wv);

    dim3 gf(LL / 64, BB * HH);           // (32, 64)
    flash_attn<<<gf, 64, smem_flash>>>(mk);

    dim3 go(DM / 128, MROWS / 128, 1);   // (8, 64)
    out_gemm<<<go, 256>>>(Wo, out);
}

// round 2
// speedup vs baseline: 1.0002x; 1.0002x over previous
#include <cuda_runtime.h>
#include <cuda_bf16.h>

// Problem constants (from reference): B=4, L=2048, D_MODEL=1024, H=16, Dh=Dv=64
#define BB 4
#define LL 2048
#define DM 1024
#define HH 16
#define DH 64
#define MROWS (BB * LL)   // 8192

// Scratch (allocation-free rule: __device__ globals)
__device__ float g_Q[MROWS * DM];
__device__ float g_K[MROWS * DM];
__device__ float g_V[MROWS * DM];
__device__ float g_ctx[MROWS * DM];

// ---------------------------------------------------------------------------
// SGEMM: C[m,n] = sum_k A[m,k] * W[n,k]   (A: M x 1024 row-major, W: 1024 x 1024
// row-major "torch Linear" layout, C: M x 1024). BM=BN=128, BK=8, 8x8 micro.
// grid: (1024/128, M/128 [, z]) block: 256
// ---------------------------------------------------------------------------
__device__ __forceinline__ void gemm_body_1024(const float* __restrict__ A,
                                               const float* __restrict__ W,
                                               float* __restrict__ C) {
    __shared__ float As[8][128];
    __shared__ float Bs[8][128];

    const int tid = threadIdx.x;
    const int tx = tid & 15;        // 0..15 -> col micro
    const int ty = tid >> 4;        // 0..15 -> row micro
    const int row0 = blockIdx.y * 128;
    const int col0 = blockIdx.x * 128;

    const int lr = tid >> 1;        // 0..127 load row
    const int lc = (tid & 1) * 4;   // 0 or 4 load col (float4)

    const float* Ap = A + (size_t)(row0 + lr) * DM + lc;
    const float* Wp = W + (size_t)(col0 + lr) * DM + lc;

    float acc[8][8];
#pragma unroll
    for (int i = 0; i < 8; ++i)
#pragma unroll
        for (int j = 0; j < 8; ++j) acc[i][j] = 0.0f;

    for (int kk = 0; kk < DM; kk += 8) {
        float4 a4 = *(const float4*)(Ap + kk);
        float4 b4 = *(const float4*)(Wp + kk);
        As[lc + 0][lr] = a4.x; As[lc + 1][lr] = a4.y;
        As[lc + 2][lr] = a4.z; As[lc + 3][lr] = a4.w;
        Bs[lc + 0][lr] = b4.x; Bs[lc + 1][lr] = b4.y;
        Bs[lc + 2][lr] = b4.z; Bs[lc + 3][lr] = b4.w;
        __syncthreads();

#pragma unroll
        for (int k = 0; k < 8; ++k) {
            float ar[8], br[8];
#pragma unroll
            for (int i = 0; i < 8; ++i) ar[i] = As[k][ty * 8 + i];
#pragma unroll
            for (int j = 0; j < 8; ++j) br[j] = Bs[k][tx * 8 + j];
#pragma unroll
            for (int i = 0; i < 8; ++i)
#pragma unroll
                for (int j = 0; j < 8; ++j)
                    acc[i][j] = fmaf(ar[i], br[j], acc[i][j]);
        }
        __syncthreads();
    }

#pragma unroll
    for (int i = 0; i < 8; ++i) {
        float* cp = C + (size_t)(row0 + ty * 8 + i) * DM + col0 + tx * 8;
        *(float4*)(cp)     = make_float4(acc[i][0], acc[i][1], acc[i][2], acc[i][3]);
        *(float4*)(cp + 4) = make_float4(acc[i][4], acc[i][5], acc[i][6], acc[i][7]);
    }
}

__global__ void __launch_bounds__(256)
qkv_gemm(const float* __restrict__ x, const float* __restrict__ Wq,
         const float* __restrict__ Wk, const float* __restrict__ Wv) {
    const float* W = (blockIdx.z == 0) ? Wq : (blockIdx.z == 1) ? Wk : Wv;
    float* C = (blockIdx.z == 0) ? g_Q : (blockIdx.z == 1) ? g_K : g_V;
    gemm_body_1024(x, W, C);
}

__global__ void __launch_bounds__(256)
out_gemm(const float* __restrict__ Wo, float* __restrict__ out) {
    gemm_body_1024(g_ctx, Wo, out);
}

// ---------------------------------------------------------------------------
// Flash attention, fp32 SIMT. Br=Bc=64, Dh=64. 64 threads (8x8 grid), each
// thread owns an 8x8 S/P tile and an 8x8 O tile. Online softmax; row
// reductions via shfl_xor over the 8 lanes that share a row group.
// grid: (L/64, B*H); block: 64; dynamic smem = 4 * 64*65 floats
// ---------------------------------------------------------------------------
#define PADW 65

__global__ void __launch_bounds__(64)
flash_attn(const unsigned char* __restrict__ mask) {
    extern __shared__ float sm[];
    float* Qs = sm;                 // [64][65]
    float* Ks = sm + 64 * PADW;     // [64][65]
    float* Vs = sm + 2 * 64 * PADW; // [64][65]
    float* Ps = sm + 3 * 64 * PADW; // [64][65]
    __shared__ unsigned char msk[64];

    const int tid = threadIdx.x;    // 0..63
    const int tx = tid & 7;         // col group
    const int ty = tid >> 3;        // row group
    const int bh = blockIdx.y;
    const int b = bh >> 4;
    const int h = bh & 15;
    const int q0 = blockIdx.x * 64;
    const size_t headoff = (size_t)b * LL * DM + (size_t)h * DH;

    // Load Q tile: one row per thread, 64 contiguous floats
    {
        const float* qr = g_Q + headoff + (size_t)(q0 + tid) * DM;
#pragma unroll
        for (int c = 0; c < 64; c += 4) {
            float4 v = *(const float4*)(qr + c);
            Qs[tid * PADW + c + 0] = v.x;
            Qs[tid * PADW + c + 1] = v.y;
            Qs[tid * PADW + c + 2] = v.z;
            Qs[tid * PADW + c + 3] = v.w;
        }
    }

    float m_i[8], l_i[8], o[8][8];
#pragma unroll
    for (int i = 0; i < 8; ++i) {
        m_i[i] = -1e30f;
        l_i[i] = 0.0f;
#pragma unroll
        for (int c = 0; c < 8; ++c) o[i][c] = 0.0f;
    }

    for (int kv0 = 0; kv0 < LL; kv0 += 64) {
        // Load K, V tiles (one row per thread) + mask bytes
        {
            const float* kr = g_K + headoff + (size_t)(kv0 + tid) * DM;
            const float* vr = g_V + headoff + (size_t)(kv0 + tid) * DM;
#pragma unroll
            for (int c = 0; c < 64; c += 4) {
                float4 kv4 = *(const float4*)(kr + c);
                Ks[tid * PADW + c + 0] = kv4.x;
                Ks[tid * PADW + c + 1] = kv4.y;
                Ks[tid * PADW + c + 2] = kv4.z;
                Ks[tid * PADW + c + 3] = kv4.w;
                float4 vv4 = *(const float4*)(vr + c);
                Vs[tid * PADW + c + 0] = vv4.x;
                Vs[tid * PADW + c + 1] = vv4.y;
                Vs[tid * PADW + c + 2] = vv4.z;
                Vs[tid * PADW + c + 3] = vv4.w;
            }
            msk[tid] = mask[(size_t)b * LL + kv0 + tid];
        }
        __syncthreads();

        // S = Q * K^T (8x8 per thread)
        float s[8][8];
#pragma unroll
        for (int i = 0; i < 8; ++i)
#pragma unroll
            for (int j = 0; j < 8; ++j) s[i][j] = 0.0f;

#pragma unroll 8
        for (int k = 0; k < 64; ++k) {
            float aq[8], bk[8];
#pragma unroll
            for (int i = 0; i < 8; ++i) aq[i] = Qs[(ty * 8 + i) * PADW + k];
#pragma unroll
            for (int j = 0; j < 8; ++j) bk[j] = Ks[(tx * 8 + j) * PADW + k];
#pragma unroll
            for (int i = 0; i < 8; ++i)
#pragma unroll
                for (int j = 0; j < 8; ++j)
                    s[i][j] = fmaf(aq[i], bk[j], s[i][j]);
        }

        // scale (1/sqrt(64)) + mask
#pragma unroll
        for (int j = 0; j < 8; ++j) {
            const bool mj = (msk[tx * 8 + j] != 0);
#pragma unroll
            for (int i = 0; i < 8; ++i)
                s[i][j] = mj ? -1e30f : s[i][j] * 0.125f;
        }

        // online softmax update + stage P into smem
#pragma unroll
        for (int i = 0; i < 8; ++i) {
            float mt = s[i][0];
#pragma unroll
            for (int j = 1; j < 8; ++j) mt = fmaxf(mt, s[i][j]);
            mt = fmaxf(mt, __shfl_xor_sync(0xffffffffu, mt, 1, 8));
            mt = fmaxf(mt, __shfl_xor_sync(0xffffffffu, mt, 2, 8));
            mt = fmaxf(mt, __shfl_xor_sync(0xffffffffu, mt, 4, 8));
            const float mn = fmaxf(m_i[i], mt);
            const float corr = __expf(m_i[i] - mn);
            m_i[i] = mn;
            float rs = 0.0f;
#pragma unroll
            for (int j = 0; j < 8; ++j) {
                const float p = __expf(s[i][j] - mn);
                s[i][j] = p;
                rs += p;
            }
            rs += __shfl_xor_sync(0xffffffffu, rs, 1, 8);
            rs += __shfl_xor_sync(0xffffffffu, rs, 2, 8);
            rs += __shfl_xor_sync(0xffffffffu, rs, 4, 8);
            l_i[i] = l_i[i] * corr + rs;
#pragma unroll
            for (int c = 0; c < 8; ++c) o[i][c] *= corr;
#pragma unroll
            for (int j = 0; j < 8; ++j)
                Ps[(ty * 8 + i) * PADW + tx * 8 + j] = s[i][j];
        }
        __syncthreads();

        // O += P * V  (8x8 per thread; cols of O are d-dims tx*8..tx*8+7)
#pragma unroll 8
        for (int j = 0; j < 64; ++j) {
            float pj[8], vj[8];
#pragma unroll
            for (int i = 0; i < 8; ++i) pj[i] = Ps[(ty * 8 + i) * PADW + j];
#pragma unroll
            for (int c = 0; c < 8; ++c) vj[c] = Vs[j * PADW + tx * 8 + c];
#pragma unroll
            for (int i = 0; i < 8; ++i)
#pragma unroll
                for (int c = 0; c < 8; ++c)
                    o[i][c] = fmaf(pj[i], vj[c], o[i][c]);
        }
        __syncthreads();
    }

    // epilogue: normalize and write ctx in (B, L, H*Dv) layout
#pragma unroll
    for (int i = 0; i < 8; ++i) {
        const float inv = 1.0f / l_i[i];
        float* op = g_ctx + headoff + (size_t)(q0 + ty * 8 + i) * DM + tx * 8;
        *(float4*)(op)     = make_float4(o[i][0] * inv, o[i][1] * inv,
                                         o[i][2] * inv, o[i][3] * inv);
        *(float4*)(op + 4) = make_float4(o[i][4] * inv, o[i][5] * inv,
                                         o[i][6] * inv, o[i][7] * inv);
    }
}

// ---------------------------------------------------------------------------
// Launch
// ---------------------------------------------------------------------------
extern "C" void kernel_launch(void* const* d_in, const int* in_sizes, int n_in,
                              void* d_out, int out_size) {
    const float* x          = (const float*)d_in[0];
    const unsigned char* mk = (const unsigned char*)d_in[1];  // all-False in this problem
    const float* Wq         = (const float*)d_in[2];
    const float* Wk         = (const float*)d_in[3];
    const float* Wv         = (const float*)d_in[4];
    const float* Wo         = (const float*)d_in[5];
    float* out              = (float*)d_out;

    const int smem_flash = 4 * 64 * PADW * (int)sizeof(float);  // 66560 B
    cudaFuncSetAttribute(flash_attn, cudaFuncAttributeMaxDynamicSharedMemorySize,
                         smem_flash);

    dim3 gq(DM / 128, MROWS / 128, 3);   // (8, 64, 3)
    qkv_gemm<<<gq, 256>>>(x, Wq, Wk, Wv);

    dim3 gf(LL / 64, BB * HH);           // (32, 64)
    flash_attn<<<gf, 64, smem_flash>>>(mk);

    dim3 go(DM / 128, MROWS / 128, 1);   // (8, 64)
    out_gemm<<<go, 256>>>(Wo, out);
}

// round 3
// speedup vs baseline: 3.0214x; 3.0207x over previous
#include <cuda_runtime.h>
#include <cuda_bf16.h>
#include <cstdint>

// Problem constants: B=4, L=2048, D_MODEL=1024, H=16, Dh=Dv=64
#define BB 4
#define LL 2048
#define DM 1024
#define HH 16
#define DH 64
#define MROWS (BB * LL)   // 8192

// Scratch (allocation-free rule: __device__ globals)
__device__ float g_Q[MROWS * DM];
__device__ float g_K[MROWS * DM];
__device__ float g_V[MROWS * DM];
__device__ float g_ctx[MROWS * DM];

// ---------------------------------------------------------------------------
// helpers
// ---------------------------------------------------------------------------
__device__ __forceinline__ unsigned f2tf(float f) {
    unsigned u;
    asm("cvt.rna.tf32.f32 %0, %1;" : "=r"(u) : "f"(f));
    return u;
}
__device__ __forceinline__ unsigned scvta(const void* p) {
    return (unsigned)__cvta_generic_to_shared(p);
}
__device__ __forceinline__ void ldsm4(unsigned& r0, unsigned& r1, unsigned& r2,
                                      unsigned& r3, unsigned a) {
    asm volatile("ldmatrix.sync.aligned.m8n8.x4.shared.b16 {%0,%1,%2,%3},[%4];"
                 : "=r"(r0), "=r"(r1), "=r"(r2), "=r"(r3) : "r"(a));
}
__device__ __forceinline__ void mma8(float* c, unsigned a0, unsigned a1,
                                     unsigned a2, unsigned a3, unsigned b0,
                                     unsigned b1) {
    asm volatile(
        "mma.sync.aligned.m16n8k8.row.col.f32.tf32.tf32.f32 "
        "{%0,%1,%2,%3},{%4,%5,%6,%7},{%8,%9},{%0,%1,%2,%3};"
        : "+f"(c[0]), "+f"(c[1]), "+f"(c[2]), "+f"(c[3])
        : "r"(a0), "r"(a1), "r"(a2), "r"(a3), "r"(b0), "r"(b1));
}

// fast exp on the FFMA pipe (x <= ~0, handles very negative -> 0)
__device__ __forceinline__ float fexp(float x) {
    float y = fmaxf(x * 1.4426950408889634f, -126.0f);
    float z = y + 12582912.0f;                 // round to int (magic)
    int   e = __float_as_int(z) << 23;         // integer part -> exponent bits
    float f = y - (z - 12582912.0f);           // frac in [-0.5, 0.5]
    float p = fmaf(1.33336e-3f, f, 9.61813e-3f);
    p = fmaf(p, f, 5.55041e-2f);
    p = fmaf(p, f, 0.240227f);
    p = fmaf(p, f, 0.693147f);
    p = fmaf(p, f, 1.0f);
    return __int_as_float(__float_as_int(p) + e);
}

// ---------------------------------------------------------------------------
// tf32 SGEMM: C[m,n] = sum_k A[m,k] * W[n,k]; 128x128 tile, BK=32, 8 warps.
// smem layout word(row,col) = row*32 + ((col/4 ^ (row&7))*4) + col%4
// ---------------------------------------------------------------------------
__device__ __forceinline__ void gemm_body(const float* __restrict__ A,
                                          const float* __restrict__ W,
                                          float* __restrict__ C) {
    __shared__ unsigned As[4096];
    __shared__ unsigned Bs[4096];
    const int tid = threadIdx.x, lane = tid & 31, warp = tid >> 5;
    const int wm = warp & 3, wn = warp >> 2;
    const int row0 = blockIdx.y * 128, col0 = blockIdx.x * 128;
    const int lsub = lane >> 3, lr = lane & 7;
    const int g = lane >> 2, tg = lane & 3;
    const unsigned asb = scvta(As), bsb = scvta(Bs);

    float c[2][8][4] = {};

    for (int kk = 0; kk < DM; kk += 32) {
#pragma unroll
        for (int p = 0; p < 4; ++p) {
            const int idx = p * 256 + tid;
            const int r = idx >> 3, q = idx & 7;
            const float4 av = *(const float4*)(A + (size_t)(row0 + r) * DM + kk + q * 4);
            const float4 bv = *(const float4*)(W + (size_t)(col0 + r) * DM + kk + q * 4);
            const int w = (r << 5) + ((q ^ (r & 7)) << 2);
            As[w + 0] = f2tf(av.x); As[w + 1] = f2tf(av.y);
            As[w + 2] = f2tf(av.z); As[w + 3] = f2tf(av.w);
            Bs[w + 0] = f2tf(bv.x); Bs[w + 1] = f2tf(bv.y);
            Bs[w + 2] = f2tf(bv.z); Bs[w + 3] = f2tf(bv.w);
        }
        __syncthreads();

#pragma unroll
        for (int ks = 0; ks < 4; ++ks) {
            const int ch = ks * 2;
            unsigned a[2][4];
#pragma unroll
            for (int mf = 0; mf < 2; ++mf) {
                const int r = wm * 32 + mf * 16 + ((lsub & 1) << 3) + lr;
                const unsigned ad =
                    asb + (((r << 5) + (((ch + (lsub >> 1)) ^ (r & 7)) << 2)) << 2);
                ldsm4(a[mf][0], a[mf][1], a[mf][2], a[mf][3], ad);
            }
#pragma unroll
            for (int np = 0; np < 4; ++np) {
                const int r = wn * 64 + np * 16 + ((lsub >> 1) << 3) + lr;
                const unsigned bd =
                    bsb + (((r << 5) + (((ch + (lsub & 1)) ^ (r & 7)) << 2)) << 2);
                unsigned b0, b1, b2, b3;
                ldsm4(b0, b1, b2, b3, bd);
#pragma unroll
                for (int mf = 0; mf < 2; ++mf) {
                    mma8(c[mf][np * 2 + 0], a[mf][0], a[mf][1], a[mf][2], a[mf][3], b0, b1);
                    mma8(c[mf][np * 2 + 1], a[mf][0], a[mf][1], a[mf][2], a[mf][3], b2, b3);
                }
            }
        }
        __syncthreads();
    }

#pragma unroll
    for (int mf = 0; mf < 2; ++mf)
#pragma unroll
        for (int nf = 0; nf < 8; ++nf) {
            const int row = row0 + wm * 32 + mf * 16 + g;
            const int col = col0 + wn * 64 + nf * 8 + 2 * tg;
            *(float2*)(C + (size_t)row * DM + col) =
                make_float2(c[mf][nf][0], c[mf][nf][1]);
            *(float2*)(C + (size_t)(row + 8) * DM + col) =
                make_float2(c[mf][nf][2], c[mf][nf][3]);
        }
}

__global__ void __launch_bounds__(256)
qkv_gemm(const float* __restrict__ x, const float* __restrict__ Wq,
         const float* __restrict__ Wk, const float* __restrict__ Wv) {
    const float* W = (blockIdx.z == 0) ? Wq : (blockIdx.z == 1) ? Wk : Wv;
    float* C = (blockIdx.z == 0) ? g_Q : (blockIdx.z == 1) ? g_K : g_V;
    gemm_body(x, W, C);
}

__global__ void __launch_bounds__(256)
out_gemm(const float* __restrict__ Wo, float* __restrict__ out) {
    gemm_body(g_ctx, Wo, out);
}

// ---------------------------------------------------------------------------
// Flash attention with tf32 mma. Block = 128 threads (4 warps), Br=64, Bc=64.
// Each warp owns 16 query rows x 64 cols. smem: Qs,Ks,Vt,Ps (64x64 tf32 each)
// word(row,col) = row*64 + ((col/4 ^ (row&7))*4) + col%4
// ---------------------------------------------------------------------------
#define ATT_SMEM (4 * 4096 * 4 + 64 * 4)

__global__ void __launch_bounds__(128)
flash_tf32(const unsigned char* __restrict__ mask) {
    extern __shared__ unsigned sm[];
    unsigned* Qs = sm;
    unsigned* Ks = sm + 4096;
    unsigned* Vt = sm + 8192;
    unsigned* Ps = sm + 12288;
    float* madd = (float*)(sm + 16384);

    const int tid = threadIdx.x, lane = tid & 31, warp = tid >> 5;
    const int lsub = lane >> 3, lr = lane & 7;
    const int g = lane >> 2, tg = lane & 3;
    const int bh = blockIdx.y, b = bh >> 4, h = bh & 15;
    const int q0 = blockIdx.x * 64;
    const size_t hoff = (size_t)b * LL * DM + (size_t)h * DH;
    const unsigned qsb = scvta(Qs), ksb = scvta(Ks), vtb = scvta(Vt), psb = scvta(Ps);

    // load Q (fold in 1/sqrt(Dh) = 0.125)
#pragma unroll
    for (int p = 0; p < 8; ++p) {
        const int idx = p * 128 + tid;
        const int r = idx >> 4, q = idx & 15;
        const float4 v = *(const float4*)(g_Q + hoff + (size_t)(q0 + r) * DM + q * 4);
        const int w = (r << 6) + ((q ^ (r & 7)) << 2);
        Qs[w + 0] = f2tf(v.x * 0.125f); Qs[w + 1] = f2tf(v.y * 0.125f);
        Qs[w + 2] = f2tf(v.z * 0.125f); Qs[w + 3] = f2tf(v.w * 0.125f);
    }

    float m0 = -1e30f, m1 = -1e30f, l0 = 0.0f, l1 = 0.0f;
    float o[8][4] = {};

    for (int kv0 = 0; kv0 < LL; kv0 += 64) {
        // K tile
#pragma unroll
        for (int p = 0; p < 8; ++p) {
            const int idx = p * 128 + tid;
            const int r = idx >> 4, q = idx & 15;
            const float4 v = *(const float4*)(g_K + hoff + (size_t)(kv0 + r) * DM + q * 4);
            const int w = (r << 6) + ((q ^ (r & 7)) << 2);
            Ks[w + 0] = f2tf(v.x); Ks[w + 1] = f2tf(v.y);
            Ks[w + 2] = f2tf(v.z); Ks[w + 3] = f2tf(v.w);
        }
        // V tile, transposed into Vt[d][key]
        {
            const int key = tid & 63, half = tid >> 6;
            const int dbase = half * 32;
#pragma unroll
            for (int dq = 0; dq < 8; ++dq) {
                const int d = dbase + dq * 4;
                const float4 v =
                    *(const float4*)(g_V + hoff + (size_t)(kv0 + key) * DM + d);
                Vt[(d + 0) * 64 + ((((key >> 2) ^ ((d + 0) & 7))) << 2) + (key & 3)] = f2tf(v.x);
                Vt[(d + 1) * 64 + ((((key >> 2) ^ ((d + 1) & 7))) << 2) + (key & 3)] = f2tf(v.y);
                Vt[(d + 2) * 64 + ((((key >> 2) ^ ((d + 2) & 7))) << 2) + (key & 3)] = f2tf(v.z);
                Vt[(d + 3) * 64 + ((((key >> 2) ^ ((d + 3) & 7))) << 2) + (key & 3)] = f2tf(v.w);
            }
        }
        if (tid < 64)
            madd[tid] = mask[(size_t)b * LL + kv0 + tid] ? -1e30f : 0.0f;
        __syncthreads();

        // S = (Q*0.125) K^T
        float s[8][4] = {};
#pragma unroll
        for (int ks = 0; ks < 8; ++ks) {
            const int ch = ks * 2;
            unsigned a0, a1, a2, a3;
            {
                const int r = warp * 16 + ((lsub & 1) << 3) + lr;
                const unsigned ad =
                    qsb + (((r << 6) + (((ch + (lsub >> 1)) ^ (r & 7)) << 2)) << 2);
                ldsm4(a0, a1, a2, a3, ad);
            }
#pragma unroll
            for (int np = 0; np < 4; ++np) {
                const int r = np * 16 + ((lsub >> 1) << 3) + lr;
                const unsigned bd =
                    ksb + (((r << 6) + (((ch + (lsub & 1)) ^ (r & 7)) << 2)) << 2);
                unsigned b0, b1, b2, b3;
                ldsm4(b0, b1, b2, b3, bd);
                mma8(s[np * 2 + 0], a0, a1, a2, a3, b0, b1);
                mma8(s[np * 2 + 1], a0, a1, a2, a3, b2, b3);
            }
        }

        // mask + online softmax
        float rm0 = -1e30f, rm1 = -1e30f;
#pragma unroll
        for (int nf = 0; nf < 8; ++nf) {
            const float2 ma = *(const float2*)&madd[nf * 8 + 2 * tg];
            s[nf][0] += ma.x; s[nf][1] += ma.y;
            s[nf][2] += ma.x; s[nf][3] += ma.y;
            rm0 = fmaxf(rm0, fmaxf(s[nf][0], s[nf][1]));
            rm1 = fmaxf(rm1, fmaxf(s[nf][2], s[nf][3]));
        }
        rm0 = fmaxf(rm0, __shfl_xor_sync(0xffffffffu, rm0, 1));
        rm0 = fmaxf(rm0, __shfl_xor_sync(0xffffffffu, rm0, 2));
        rm1 = fmaxf(rm1, __shfl_xor_sync(0xffffffffu, rm1, 1));
        rm1 = fmaxf(rm1, __shfl_xor_sync(0xffffffffu, rm1, 2));
        const float mn0 = fmaxf(m0, rm0), mn1 = fmaxf(m1, rm1);
        const float corr0 = fexp(m0 - mn0), corr1 = fexp(m1 - mn1);
        m0 = mn0; m1 = mn1;

        float rs0 = 0.0f, rs1 = 0.0f;
        const int prow0 = warp * 16 + g;
#pragma unroll
        for (int nf = 0; nf < 8; ++nf) {
            const float p0 = fexp(s[nf][0] - mn0);
            const float p1 = fexp(s[nf][1] - mn0);
            const float p2 = fexp(s[nf][2] - mn1);
            const float p3 = fexp(s[nf][3] - mn1);
            rs0 += p0 + p1; rs1 += p2 + p3;
            const int col = nf * 8 + 2 * tg;
            const int w0 = (prow0 << 6) + ((((col >> 2) ^ (prow0 & 7))) << 2) + (col & 3);
            *(uint2*)&Ps[w0] = make_uint2(f2tf(p0), f2tf(p1));
            const int prow1 = prow0 + 8;
            const int w1 = (prow1 << 6) + ((((col >> 2) ^ (prow1 & 7))) << 2) + (col & 3);
            *(uint2*)&Ps[w1] = make_uint2(f2tf(p2), f2tf(p3));
        }
        rs0 += __shfl_xor_sync(0xffffffffu, rs0, 1);
        rs0 += __shfl_xor_sync(0xffffffffu, rs0, 2);
        rs1 += __shfl_xor_sync(0xffffffffu, rs1, 1);
        rs1 += __shfl_xor_sync(0xffffffffu, rs1, 2);
        l0 = l0 * corr0 + rs0;
        l1 = l1 * corr1 + rs1;
#pragma unroll
        for (int nf = 0; nf < 8; ++nf) {
            o[nf][0] *= corr0; o[nf][1] *= corr0;
            o[nf][2] *= corr1; o[nf][3] *= corr1;
        }
        __syncwarp();

        // O += P V   (A = Ps rows, B = Vt[d][key])
#pragma unroll
        for (int ks = 0; ks < 8; ++ks) {
            const int ch = ks * 2;
            unsigned a0, a1, a2, a3;
            {
                const int r = warp * 16 + ((lsub & 1) << 3) + lr;
                const unsigned ad =
                    psb + (((r << 6) + (((ch + (lsub >> 1)) ^ (r & 7)) << 2)) << 2);
                ldsm4(a0, a1, a2, a3, ad);
            }
#pragma unroll
            for (int np = 0; np < 4; ++np) {
                const int rv = np * 16 + ((lsub >> 1) << 3) + lr;
                const unsigned bd =
                    vtb + (((rv << 6) + (((ch + (lsub & 1)) ^ (rv & 7)) << 2)) << 2);
                unsigned b0, b1, b2, b3;
                ldsm4(b0, b1, b2, b3, bd);
                mma8(o[np * 2 + 0], a0, a1, a2, a3, b0, b1);
                mma8(o[np * 2 + 1], a0, a1, a2, a3, b2, b3);
            }
        }
        __syncthreads();
    }

    // epilogue -> g_ctx (B, L, H*Dv)
    const float inv0 = 1.0f / l0, inv1 = 1.0f / l1;
#pragma unroll
    for (int nf = 0; nf < 8; ++nf) {
        const int row = q0 + warp * 16 + g;
        const int col = nf * 8 + 2 * tg;
        *(float2*)(g_ctx + hoff + (size_t)row * DM + col) =
            make_float2(o[nf][0] * inv0, o[nf][1] * inv0);
        *(float2*)(g_ctx + hoff + (size_t)(row + 8) * DM + col) =
            make_float2(o[nf][2] * inv1, o[nf][3] * inv1);
    }
}

// ---------------------------------------------------------------------------
// Launch
// ---------------------------------------------------------------------------
extern "C" void kernel_launch(void* const* d_in, const int* in_sizes, int n_in,
                              void* d_out, int out_size) {
    const float* x          = (const float*)d_in[0];
    const unsigned char* mk = (const unsigned char*)d_in[1];
    const float* Wq         = (const float*)d_in[2];
    const float* Wk         = (const float*)d_in[3];
    const float* Wv         = (const float*)d_in[4];
    const float* Wo         = (const float*)d_in[5];
    float* out              = (float*)d_out;

    cudaFuncSetAttribute(flash_tf32, cudaFuncAttributeMaxDynamicSharedMemorySize,
                         ATT_SMEM);

    dim3 gq(DM / 128, MROWS / 128, 3);
    qkv_gemm<<<gq, 256>>>(x, Wq, Wk, Wv);

    dim3 gf(LL / 64, BB * HH);
    flash_tf32<<<gf, 128, ATT_SMEM>>>(mk);

    dim3 go(DM / 128, MROWS / 128, 1);
    out_gemm<<<go, 256>>>(Wo, out);
}

// round 4
// speedup vs baseline: 3.4962x; 1.1572x over previous
#include <cuda_runtime.h>
#include <cuda_bf16.h>
#include <cstdint>

// Problem constants: B=4, L=2048, D_MODEL=1024, H=16, Dh=Dv=64
#define BB 4
#define LL 2048
#define DM 1024
#define HH 16
#define DH 64
#define MROWS (BB * LL)   // 8192

__device__ float g_Q[MROWS * DM];
__device__ float g_K[MROWS * DM];
__device__ float g_V[MROWS * DM];
__device__ float g_ctx[MROWS * DM];

// ---------------------------------------------------------------------------
// helpers
// ---------------------------------------------------------------------------
__device__ __forceinline__ unsigned f2tf(float f) {
    unsigned u;
    asm("cvt.rna.tf32.f32 %0, %1;" : "=r"(u) : "f"(f));
    return u;
}
__device__ __forceinline__ unsigned scvta(const void* p) {
    return (unsigned)__cvta_generic_to_shared(p);
}
__device__ __forceinline__ void ldsm4(unsigned& r0, unsigned& r1, unsigned& r2,
                                      unsigned& r3, unsigned a) {
    asm volatile("ldmatrix.sync.aligned.m8n8.x4.shared.b16 {%0,%1,%2,%3},[%4];"
                 : "=r"(r0), "=r"(r1), "=r"(r2), "=r"(r3) : "r"(a));
}
__device__ __forceinline__ void mma8(float* c, unsigned a0, unsigned a1,
                                     unsigned a2, unsigned a3, unsigned b0,
                                     unsigned b1) {
    asm volatile(
        "mma.sync.aligned.m16n8k8.row.col.f32.tf32.tf32.f32 "
        "{%0,%1,%2,%3},{%4,%5,%6,%7},{%8,%9},{%0,%1,%2,%3};"
        : "+f"(c[0]), "+f"(c[1]), "+f"(c[2]), "+f"(c[3])
        : "r"(a0), "r"(a1), "r"(a2), "r"(a3), "r"(b0), "r"(b1));
}

// fast exp2-based exp on the FFMA pipe
__device__ __forceinline__ float fexp(float x) {
    float y = fmaxf(x * 1.4426950408889634f, -126.0f);
    float z = y + 12582912.0f;
    int   e = __float_as_int(z) << 23;
    float f = y - (z - 12582912.0f);
    float p = fmaf(1.33336e-3f, f, 9.61813e-3f);
    p = fmaf(p, f, 5.55041e-2f);
    p = fmaf(p, f, 0.240227f);
    p = fmaf(p, f, 0.693147f);
    p = fmaf(p, f, 1.0f);
    return __int_as_float(__float_as_int(p) + e);
}

// ---------------------------------------------------------------------------
// tf32 SGEMM (unchanged from R2): C[m,n] = sum_k A[m,k]*W[n,k]; 128x128, BK=32
// ---------------------------------------------------------------------------
__device__ __forceinline__ void gemm_body(const float* __restrict__ A,
                                          const float* __restrict__ W,
                                          float* __restrict__ C) {
    __shared__ unsigned As[4096];
    __shared__ unsigned Bs[4096];
    const int tid = threadIdx.x, lane = tid & 31, warp = tid >> 5;
    const int wm = warp & 3, wn = warp >> 2;
    const int row0 = blockIdx.y * 128, col0 = blockIdx.x * 128;
    const int lsub = lane >> 3, lr = lane & 7;
    const int g = lane >> 2, tg = lane & 3;
    const unsigned asb = scvta(As), bsb = scvta(Bs);

    float c[2][8][4] = {};

    for (int kk = 0; kk < DM; kk += 32) {
#pragma unroll
        for (int p = 0; p < 4; ++p) {
            const int idx = p * 256 + tid;
            const int r = idx >> 3, q = idx & 7;
            const float4 av = *(const float4*)(A + (size_t)(row0 + r) * DM + kk + q * 4);
            const float4 bv = *(const float4*)(W + (size_t)(col0 + r) * DM + kk + q * 4);
            const int w = (r << 5) + ((q ^ (r & 7)) << 2);
            As[w + 0] = f2tf(av.x); As[w + 1] = f2tf(av.y);
            As[w + 2] = f2tf(av.z); As[w + 3] = f2tf(av.w);
            Bs[w + 0] = f2tf(bv.x); Bs[w + 1] = f2tf(bv.y);
            Bs[w + 2] = f2tf(bv.z); Bs[w + 3] = f2tf(bv.w);
        }
        __syncthreads();

#pragma unroll
        for (int ks = 0; ks < 4; ++ks) {
            const int ch = ks * 2;
            unsigned a[2][4];
#pragma unroll
            for (int mf = 0; mf < 2; ++mf) {
                const int r = wm * 32 + mf * 16 + ((lsub & 1) << 3) + lr;
                const unsigned ad =
                    asb + (((r << 5) + (((ch + (lsub >> 1)) ^ (r & 7)) << 2)) << 2);
                ldsm4(a[mf][0], a[mf][1], a[mf][2], a[mf][3], ad);
            }
#pragma unroll
            for (int np = 0; np < 4; ++np) {
                const int r = wn * 64 + np * 16 + ((lsub >> 1) << 3) + lr;
                const unsigned bd =
                    bsb + (((r << 5) + (((ch + (lsub & 1)) ^ (r & 7)) << 2)) << 2);
                unsigned b0, b1, b2, b3;
                ldsm4(b0, b1, b2, b3, bd);
#pragma unroll
                for (int mf = 0; mf < 2; ++mf) {
                    mma8(c[mf][np * 2 + 0], a[mf][0], a[mf][1], a[mf][2], a[mf][3], b0, b1);
                    mma8(c[mf][np * 2 + 1], a[mf][0], a[mf][1], a[mf][2], a[mf][3], b2, b3);
                }
            }
        }
        __syncthreads();
    }

#pragma unroll
    for (int mf = 0; mf < 2; ++mf)
#pragma unroll
        for (int nf = 0; nf < 8; ++nf) {
            const int row = row0 + wm * 32 + mf * 16 + g;
            const int col = col0 + wn * 64 + nf * 8 + 2 * tg;
            *(float2*)(C + (size_t)row * DM + col) =
                make_float2(c[mf][nf][0], c[mf][nf][1]);
            *(float2*)(C + (size_t)(row + 8) * DM + col) =
                make_float2(c[mf][nf][2], c[mf][nf][3]);
        }
}

__global__ void __launch_bounds__(256)
qkv_gemm(const float* __restrict__ x, const float* __restrict__ Wq,
         const float* __restrict__ Wk, const float* __restrict__ Wv) {
    const float* W = (blockIdx.z == 0) ? Wq : (blockIdx.z == 1) ? Wk : Wv;
    float* C = (blockIdx.z == 0) ? g_Q : (blockIdx.z == 1) ? g_K : g_V;
    gemm_body(x, W, C);
}

__global__ void __launch_bounds__(256)
out_gemm(const float* __restrict__ Wo, float* __restrict__ out) {
    gemm_body(g_ctx, Wo, out);
}

// ---------------------------------------------------------------------------
// Flash attention, tf32 mma. Block = 128 threads (4 warps). Br=128 (32 rows
// per warp -> B fragments amortized over 2x rows vs R2), Bc=64.
// smem ~96KB -> 2 CTAs/SM for latency overlap.
// word(row,col) = row*64 + ((col/4 ^ (row&7))*4) + col%4
// ---------------------------------------------------------------------------
#define ATT_WORDS (8192 + 4096 + 4096 + 8192)
#define ATT_SMEM (ATT_WORDS * 4 + 64 * 4)

__global__ void __launch_bounds__(128)
flash_tf32(const unsigned char* __restrict__ mask) {
    extern __shared__ unsigned sm[];
    unsigned* Qs = sm;            // 128x64
    unsigned* Ks = sm + 8192;     // 64x64
    unsigned* Vt = sm + 12288;    // 64x64 (rows = d, cols = key)
    unsigned* Ps = sm + 16384;    // 128x64
    float* madd = (float*)(sm + ATT_WORDS);

    const int tid = threadIdx.x, lane = tid & 31, warp = tid >> 5;
    const int lsub = lane >> 3, lr = lane & 7;
    const int g = lane >> 2, tg = lane & 3;
    const int bh = blockIdx.y, b = bh >> 4, h = bh & 15;
    const int q0 = blockIdx.x * 128;
    const size_t hoff = (size_t)b * LL * DM + (size_t)h * DH;
    const unsigned qsb = scvta(Qs), ksb = scvta(Ks), vtb = scvta(Vt), psb = scvta(Ps);

    // load Q (fold in 1/sqrt(Dh) = 0.125): 128 rows x 16 words
#pragma unroll
    for (int p = 0; p < 16; ++p) {
        const int idx = p * 128 + tid;
        const int r = idx >> 4, q = idx & 15;
        const float4 v = *(const float4*)(g_Q + hoff + (size_t)(q0 + r) * DM + q * 4);
        const int w = (r << 6) + ((q ^ (r & 7)) << 2);
        Qs[w + 0] = f2tf(v.x * 0.125f); Qs[w + 1] = f2tf(v.y * 0.125f);
        Qs[w + 2] = f2tf(v.z * 0.125f); Qs[w + 3] = f2tf(v.w * 0.125f);
    }

    // per-thread stats: rows (warp*32 + mf*16 + g) and (+8)
    float m[2][2], l[2][2];
#pragma unroll
    for (int mf = 0; mf < 2; ++mf) { m[mf][0] = m[mf][1] = -1e30f; l[mf][0] = l[mf][1] = 0.0f; }
    float o[2][8][4] = {};

    for (int kv0 = 0; kv0 < LL; kv0 += 64) {
        // K tile: 64 rows x 16 words
#pragma unroll
        for (int p = 0; p < 8; ++p) {
            const int idx = p * 128 + tid;
            const int r = idx >> 4, q = idx & 15;
            const float4 v = *(const float4*)(g_K + hoff + (size_t)(kv0 + r) * DM + q * 4);
            const int w = (r << 6) + ((q ^ (r & 7)) << 2);
            Ks[w + 0] = f2tf(v.x); Ks[w + 1] = f2tf(v.y);
            Ks[w + 2] = f2tf(v.z); Ks[w + 3] = f2tf(v.w);
        }
        // V tile transposed into Vt[d][key]
        {
            const int key = tid & 63, half = tid >> 6;
#pragma unroll
            for (int dq = 0; dq < 8; ++dq) {
                const int d = half * 32 + dq * 4;
                const float4 v =
                    *(const float4*)(g_V + hoff + (size_t)(kv0 + key) * DM + d);
                Vt[(d + 0) * 64 + ((((key >> 2) ^ ((d + 0) & 7))) << 2) + (key & 3)] = f2tf(v.x);
                Vt[(d + 1) * 64 + ((((key >> 2) ^ ((d + 1) & 7))) << 2) + (key & 3)] = f2tf(v.y);
                Vt[(d + 2) * 64 + ((((key >> 2) ^ ((d + 2) & 7))) << 2) + (key & 3)] = f2tf(v.z);
                Vt[(d + 3) * 64 + ((((key >> 2) ^ ((d + 3) & 7))) << 2) + (key & 3)] = f2tf(v.w);
            }
        }
        if (tid < 64)
            madd[tid] = mask[(size_t)b * LL + kv0 + tid] ? -1e30f : 0.0f;
        __syncthreads();

        // S = (Q*0.125) K^T : per warp 32 rows x 64 keys
        float s[2][8][4] = {};
#pragma unroll
        for (int ks = 0; ks < 8; ++ks) {
            const int ch = ks * 2;
            unsigned a[2][4];
#pragma unroll
            for (int mf = 0; mf < 2; ++mf) {
                const int r = warp * 32 + mf * 16 + ((lsub & 1) << 3) + lr;
                const unsigned ad =
                    qsb + (((r << 6) + (((ch + (lsub >> 1)) ^ (r & 7)) << 2)) << 2);
                ldsm4(a[mf][0], a[mf][1], a[mf][2], a[mf][3], ad);
            }
#pragma unroll
            for (int np = 0; np < 4; ++np) {
                const int r = np * 16 + ((lsub >> 1) << 3) + lr;
                const unsigned bd =
                    ksb + (((r << 6) + (((ch + (lsub & 1)) ^ (r & 7)) << 2)) << 2);
                unsigned b0, b1, b2, b3;
                ldsm4(b0, b1, b2, b3, bd);
#pragma unroll
                for (int mf = 0; mf < 2; ++mf) {
                    mma8(s[mf][np * 2 + 0], a[mf][0], a[mf][1], a[mf][2], a[mf][3], b0, b1);
                    mma8(s[mf][np * 2 + 1], a[mf][0], a[mf][1], a[mf][2], a[mf][3], b2, b3);
                }
            }
        }

        // mask + online softmax (per mf fragment: rows g and g+8)
#pragma unroll
        for (int mf = 0; mf < 2; ++mf) {
            float rm0 = -1e30f, rm1 = -1e30f;
#pragma unroll
            for (int nf = 0; nf < 8; ++nf) {
                const float2 ma = *(const float2*)&madd[nf * 8 + 2 * tg];
                s[mf][nf][0] += ma.x; s[mf][nf][1] += ma.y;
                s[mf][nf][2] += ma.x; s[mf][nf][3] += ma.y;
                rm0 = fmaxf(rm0, fmaxf(s[mf][nf][0], s[mf][nf][1]));
                rm1 = fmaxf(rm1, fmaxf(s[mf][nf][2], s[mf][nf][3]));
            }
            rm0 = fmaxf(rm0, __shfl_xor_sync(0xffffffffu, rm0, 1));
            rm0 = fmaxf(rm0, __shfl_xor_sync(0xffffffffu, rm0, 2));
            rm1 = fmaxf(rm1, __shfl_xor_sync(0xffffffffu, rm1, 1));
            rm1 = fmaxf(rm1, __shfl_xor_sync(0xffffffffu, rm1, 2));
            const float mn0 = fmaxf(m[mf][0], rm0), mn1 = fmaxf(m[mf][1], rm1);
            const float corr0 = fexp(m[mf][0] - mn0), corr1 = fexp(m[mf][1] - mn1);
            m[mf][0] = mn0; m[mf][1] = mn1;

            float rs0 = 0.0f, rs1 = 0.0f;
            const int prow0 = warp * 32 + mf * 16 + g;
#pragma unroll
            for (int nf = 0; nf < 8; ++nf) {
                const float p0 = fexp(s[mf][nf][0] - mn0);
                const float p1 = fexp(s[mf][nf][1] - mn0);
                const float p2 = fexp(s[mf][nf][2] - mn1);
                const float p3 = fexp(s[mf][nf][3] - mn1);
                rs0 += p0 + p1; rs1 += p2 + p3;
                const int col = nf * 8 + 2 * tg;
                const int w0 = (prow0 << 6) + ((((col >> 2) ^ (prow0 & 7))) << 2) + (col & 3);
                *(uint2*)&Ps[w0] = make_uint2(f2tf(p0), f2tf(p1));
                const int prow1 = prow0 + 8;
                const int w1 = (prow1 << 6) + ((((col >> 2) ^ (prow1 & 7))) << 2) + (col & 3);
                *(uint2*)&Ps[w1] = make_uint2(f2tf(p2), f2tf(p3));
            }
            rs0 += __shfl_xor_sync(0xffffffffu, rs0, 1);
            rs0 += __shfl_xor_sync(0xffffffffu, rs0, 2);
            rs1 += __shfl_xor_sync(0xffffffffu, rs1, 1);
            rs1 += __shfl_xor_sync(0xffffffffu, rs1, 2);
            l[mf][0] = l[mf][0] * corr0 + rs0;
            l[mf][1] = l[mf][1] * corr1 + rs1;
#pragma unroll
            for (int nf = 0; nf < 8; ++nf) {
                o[mf][nf][0] *= corr0; o[mf][nf][1] *= corr0;
                o[mf][nf][2] *= corr1; o[mf][nf][3] *= corr1;
            }
        }
        __syncwarp();

        // O += P V   (A = Ps rows [this warp's 32], B = Vt[d][key])
#pragma unroll
        for (int ks = 0; ks < 8; ++ks) {
            const int ch = ks * 2;
            unsigned a[2][4];
#pragma unroll
            for (int mf = 0; mf < 2; ++mf) {
                const int r = warp * 32 + mf * 16 + ((lsub & 1) << 3) + lr;
                const unsigned ad =
                    psb + (((r << 6) + (((ch + (lsub >> 1)) ^ (r & 7)) << 2)) << 2);
                ldsm4(a[mf][0], a[mf][1], a[mf][2], a[mf][3], ad);
            }
#pragma unroll
            for (int np = 0; np < 4; ++np) {
                const int rv = np * 16 + ((lsub >> 1) << 3) + lr;
                const unsigned bd =
                    vtb + (((rv << 6) + (((ch + (lsub & 1)) ^ (rv & 7)) << 2)) << 2);
                unsigned b0, b1, b2, b3;
                ldsm4(b0, b1, b2, b3, bd);
#pragma unroll
                for (int mf = 0; mf < 2; ++mf) {
                    mma8(o[mf][np * 2 + 0], a[mf][0], a[mf][1], a[mf][2], a[mf][3], b0, b1);
                    mma8(o[mf][np * 2 + 1], a[mf][0], a[mf][1], a[mf][2], a[mf][3], b2, b3);
                }
            }
        }
        __syncthreads();
    }

    // epilogue -> g_ctx (B, L, H*Dv)
#pragma unroll
    for (int mf = 0; mf < 2; ++mf) {
        const float inv0 = 1.0f / l[mf][0], inv1 = 1.0f / l[mf][1];
#pragma unroll
        for (int nf = 0; nf < 8; ++nf) {
            const int row = q0 + warp * 32 + mf * 16 + g;
            const int col = nf * 8 + 2 * tg;
            *(float2*)(g_ctx + hoff + (size_t)row * DM + col) =
                make_float2(o[mf][nf][0] * inv0, o[mf][nf][1] * inv0);
            *(float2*)(g_ctx + hoff + (size_t)(row + 8) * DM + col) =
                make_float2(o[mf][nf][2] * inv1, o[mf][nf][3] * inv1);
        }
    }
}

// ---------------------------------------------------------------------------
// Launch
// ---------------------------------------------------------------------------
extern "C" void kernel_launch(void* const* d_in, const int* in_sizes, int n_in,
                              void* d_out, int out_size) {
    const float* x          = (const float*)d_in[0];
    const unsigned char* mk = (const unsigned char*)d_in[1];
    const float* Wq         = (const float*)d_in[2];
    const float* Wk         = (const float*)d_in[3];
    const float* Wv         = (const float*)d_in[4];
    const float* Wo         = (const float*)d_in[5];
    float* out              = (float*)d_out;

    cudaFuncSetAttribute(flash_tf32, cudaFuncAttributeMaxDynamicSharedMemorySize,
                         ATT_SMEM);

    dim3 gq(DM / 128, MROWS / 128, 3);
    qkv_gemm<<<gq, 256>>>(x, Wq, Wk, Wv);

    dim3 gf(LL / 128, BB * HH);
    flash_tf32<<<gf, 128, ATT_SMEM>>>(mk);

    dim3 go(DM / 128, MROWS / 128, 1);
    out_gemm<<<go, 256>>>(Wo, out);
}

// round 6
// speedup vs baseline: 3.5004x; 1.0012x over previous
#include <cuda_runtime.h>
#include <cuda_bf16.h>
#include <cstdint>

// Problem constants: B=4, L=2048, D_MODEL=1024, H=16, Dh=Dv=64
#define BB 4
#define LL 2048
#define DM 1024
#define HH 16
#define DH 64
#define MROWS (BB * LL)   // 8192

__device__ float g_Q[MROWS * DM];
__device__ float g_K[MROWS * DM];
__device__ float g_V[MROWS * DM];
__device__ float g_ctx[MROWS * DM];

// ---------------------------------------------------------------------------
// helpers
// ---------------------------------------------------------------------------
__device__ __forceinline__ unsigned f2tf(float f) {
    unsigned u;
    asm("cvt.rna.tf32.f32 %0, %1;" : "=r"(u) : "f"(f));
    return u;
}
__device__ __forceinline__ unsigned scvta(const void* p) {
    return (unsigned)__cvta_generic_to_shared(p);
}
__device__ __forceinline__ void ldsm4(unsigned& r0, unsigned& r1, unsigned& r2,
                                      unsigned& r3, unsigned a) {
    asm volatile("ldmatrix.sync.aligned.m8n8.x4.shared.b16 {%0,%1,%2,%3},[%4];"
                 : "=r"(r0), "=r"(r1), "=r"(r2), "=r"(r3) : "r"(a));
}
__device__ __forceinline__ void mma8(float* c, unsigned a0, unsigned a1,
                                     unsigned a2, unsigned a3, unsigned b0,
                                     unsigned b1) {
    asm volatile(
        "mma.sync.aligned.m16n8k8.row.col.f32.tf32.tf32.f32 "
        "{%0,%1,%2,%3},{%4,%5,%6,%7},{%8,%9},{%0,%1,%2,%3};"
        : "+f"(c[0]), "+f"(c[1]), "+f"(c[2]), "+f"(c[3])
        : "r"(a0), "r"(a1), "r"(a2), "r"(a3), "r"(b0), "r"(b1));
}
__device__ __forceinline__ float fexp(float x) {
    float y = fmaxf(x * 1.4426950408889634f, -126.0f);
    float z = y + 12582912.0f;
    int   e = __float_as_int(z) << 23;
    float f = y - (z - 12582912.0f);
    float p = fmaf(1.33336e-3f, f, 9.61813e-3f);
    p = fmaf(p, f, 5.55041e-2f);
    p = fmaf(p, f, 0.240227f);
    p = fmaf(p, f, 0.693147f);
    p = fmaf(p, f, 1.0f);
    return __int_as_float(__float_as_int(p) + e);
}

// ---------------------------------------------------------------------------
// tf32 SGEMM v2: C[m,n] = sum_k A[m,k] * W[n,k]
// Tile 256x128, BK=32, 8 warps, warp tile 64x64 (LDSM/mma ratio 1.5x better).
// Register prefetch of next chunk issued before compute.
// smem word(row,col) = row*32 + ((col/4 ^ (row&7))*4) + col%4
// ---------------------------------------------------------------------------
#define GEMM_SMEM 49152   // A: 256x32 words (32KB) + B: 128x32 words (16KB)

__device__ __forceinline__ void gemm_body(const float* __restrict__ A,
                                          const float* __restrict__ W,
                                          float* __restrict__ C) {
    extern __shared__ unsigned gsm[];
    unsigned* As = gsm;          // 8192 words
    unsigned* Bs = gsm + 8192;   // 4096 words

    const int tid = threadIdx.x, lane = tid & 31, warp = tid >> 5;
    const int wm = warp & 3, wn = warp >> 2;     // 4 row-groups x 2 col-groups
    const int row0 = blockIdx.y * 256, col0 = blockIdx.x * 128;
    const int lsub = lane >> 3, lr = lane & 7;
    const int g = lane >> 2, tg = lane & 3;
    const unsigned asb = scvta(As), bsb = scvta(Bs);

    // load geometry
    int ar[8], aq[8], asw[8];
#pragma unroll
    for (int p = 0; p < 8; ++p) {
        const int i = p * 256 + tid;      // 2048 float4 for A
        ar[p] = i >> 3; aq[p] = i & 7;
        asw[p] = (ar[p] << 5) + ((aq[p] ^ (ar[p] & 7)) << 2);
    }
    int br[4], bq[4], bsw[4];
#pragma unroll
    for (int p = 0; p < 4; ++p) {
        const int i = p * 256 + tid;      // 1024 float4 for B
        br[p] = i >> 3; bq[p] = i & 7;
        bsw[p] = (br[p] << 5) + ((bq[p] ^ (br[p] & 7)) << 2);
    }

    float acc[4][8][4] = {};
    float4 av[8], bv[4];

    // prologue: chunk 0 into regs
#pragma unroll
    for (int p = 0; p < 8; ++p)
        av[p] = *(const float4*)(A + (size_t)(row0 + ar[p]) * DM + aq[p] * 4);
#pragma unroll
    for (int p = 0; p < 4; ++p)
        bv[p] = *(const float4*)(W + (size_t)(col0 + br[p]) * DM + bq[p] * 4);

    for (int c = 0; c < 32; ++c) {
        // store current chunk to smem (tf32-converted)
#pragma unroll
        for (int p = 0; p < 8; ++p) {
            uint4 u;
            u.x = f2tf(av[p].x); u.y = f2tf(av[p].y);
            u.z = f2tf(av[p].z); u.w = f2tf(av[p].w);
            *(uint4*)(As + asw[p]) = u;
        }
#pragma unroll
        for (int p = 0; p < 4; ++p) {
            uint4 u;
            u.x = f2tf(bv[p].x); u.y = f2tf(bv[p].y);
            u.z = f2tf(bv[p].z); u.w = f2tf(bv[p].w);
            *(uint4*)(Bs + bsw[p]) = u;
        }
        __syncthreads();

        // prefetch next chunk (latency hidden under the mma block below)
        if (c < 31) {
            const int kk = (c + 1) * 32;
#pragma unroll
            for (int p = 0; p < 8; ++p)
                av[p] = *(const float4*)(A + (size_t)(row0 + ar[p]) * DM + kk + aq[p] * 4);
#pragma unroll
            for (int p = 0; p < 4; ++p)
                bv[p] = *(const float4*)(W + (size_t)(col0 + br[p]) * DM + kk + bq[p] * 4);
        }

#pragma unroll
        for (int ks = 0; ks < 4; ++ks) {
            const int ch = ks * 2;
            unsigned a[4][4], b[4][4];
#pragma unroll
            for (int mf = 0; mf < 4; ++mf) {
                const int r = wm * 64 + mf * 16 + ((lsub & 1) << 3) + lr;
                const unsigned ad =
                    asb + (((r << 5) + (((ch + (lsub >> 1)) ^ (r & 7)) << 2)) << 2);
                ldsm4(a[mf][0], a[mf][1], a[mf][2], a[mf][3], ad);
            }
#pragma unroll
            for (int np = 0; np < 4; ++np) {
                const int r = wn * 64 + np * 16 + ((lsub >> 1) << 3) + lr;
                const unsigned bd =
                    bsb + (((r << 5) + (((ch + (lsub & 1)) ^ (r & 7)) << 2)) << 2);
                ldsm4(b[np][0], b[np][1], b[np][2], b[np][3], bd);
            }
#pragma unroll
            for (int mf = 0; mf < 4; ++mf)
#pragma unroll
                for (int np = 0; np < 4; ++np) {
                    mma8(acc[mf][np * 2 + 0], a[mf][0], a[mf][1], a[mf][2], a[mf][3],
                         b[np][0], b[np][1]);
                    mma8(acc[mf][np * 2 + 1], a[mf][0], a[mf][1], a[mf][2], a[mf][3],
                         b[np][2], b[np][3]);
                }
        }
        __syncthreads();
    }

#pragma unroll
    for (int mf = 0; mf < 4; ++mf)
#pragma unroll
        for (int nf = 0; nf < 8; ++nf) {
            const int row = row0 + wm * 64 + mf * 16 + g;
            const int col = col0 + wn * 64 + nf * 8 + 2 * tg;
            *(float2*)(C + (size_t)row * DM + col) =
                make_float2(acc[mf][nf][0], acc[mf][nf][1]);
            *(float2*)(C + (size_t)(row + 8) * DM + col) =
                make_float2(acc[mf][nf][2], acc[mf][nf][3]);
        }
}

__global__ void __launch_bounds__(256, 1)
qkv_gemm(const float* __restrict__ x, const float* __restrict__ Wq,
         const float* __restrict__ Wk, const float* __restrict__ Wv) {
    const float* W = (blockIdx.z == 0) ? Wq : (blockIdx.z == 1) ? Wk : Wv;
    float* C = (blockIdx.z == 0) ? g_Q : (blockIdx.z == 1) ? g_K : g_V;
    gemm_body(x, W, C);
}

__global__ void __launch_bounds__(256, 1)
out_gemm(const float* __restrict__ Wo, float* __restrict__ out) {
    gemm_body(g_ctx, Wo, out);
}

// ---------------------------------------------------------------------------
// Flash attention, tf32 mma.sync. 128 threads (4 warps), Br=128, Bc=64,
// 32 q-rows per warp. K prefetched before QK, V/mask before PV (reg-staged).
// word(row,col) = row*64 + ((col/4 ^ (row&7))*4) + col%4
// ---------------------------------------------------------------------------
#define ATT_WORDS (8192 + 4096 + 4096 + 8192)
#define ATT_SMEM (ATT_WORDS * 4 + 64 * 4)

__global__ void __launch_bounds__(128)
flash_tf32(const unsigned char* __restrict__ mask) {
    extern __shared__ unsigned sm[];
    unsigned* Qs = sm;            // 128x64
    unsigned* Ks = sm + 8192;     // 64x64
    unsigned* Vt = sm + 12288;    // 64x64 (rows = d, cols = key)
    unsigned* Ps = sm + 16384;    // 128x64
    float* madd = (float*)(sm + ATT_WORDS);

    const int tid = threadIdx.x, lane = tid & 31, warp = tid >> 5;
    const int lsub = lane >> 3, lr = lane & 7;
    const int g = lane >> 2, tg = lane & 3;
    const int bh = blockIdx.y, b = bh >> 4, h = bh & 15;
    const int q0 = blockIdx.x * 128;
    const size_t hoff = (size_t)b * LL * DM + (size_t)h * DH;
    const unsigned qsb = scvta(Qs), ksb = scvta(Ks), vtb = scvta(Vt), psb = scvta(Ps);

    // K/V load geometry
    const int krow[2] = {(tid >> 4), 8 + (tid >> 4)};          // via p loop
    (void)krow;
    const int vkey = tid & 63, vhalf = tid >> 6;

    float4 kv_k[8];        // next K tile (8 float4/thread)
    float4 kv_v[8];        // next V tile
    unsigned char mv = 0;

    // prologue: Q tile staged (scaled), first K/V into regs
#pragma unroll
    for (int p = 0; p < 16; ++p) {
        const int idx = p * 128 + tid;
        const int r = idx >> 4, q = idx & 15;
        const float4 v = *(const float4*)(g_Q + hoff + (size_t)(q0 + r) * DM + q * 4);
        const int w = (r << 6) + ((q ^ (r & 7)) << 2);
        Qs[w + 0] = f2tf(v.x * 0.125f); Qs[w + 1] = f2tf(v.y * 0.125f);
        Qs[w + 2] = f2tf(v.z * 0.125f); Qs[w + 3] = f2tf(v.w * 0.125f);
    }
#pragma unroll
    for (int p = 0; p < 8; ++p) {
        const int idx = p * 128 + tid;
        const int r = idx >> 4, q = idx & 15;
        kv_k[p] = *(const float4*)(g_K + hoff + (size_t)r * DM + q * 4);
    }
#pragma unroll
    for (int dq = 0; dq < 8; ++dq) {
        const int d = vhalf * 32 + dq * 4;
        kv_v[dq] = *(const float4*)(g_V + hoff + (size_t)vkey * DM + d);
    }
    if (tid < 64) mv = mask[(size_t)b * LL + tid];

    float m[2][2], l[2][2];
#pragma unroll
    for (int mf = 0; mf < 2; ++mf) { m[mf][0] = m[mf][1] = -1e30f; l[mf][0] = l[mf][1] = 0.0f; }
    float o[2][8][4] = {};

    for (int kv0 = 0; kv0 < LL; kv0 += 64) {
        // store staged K/V/mask to smem
#pragma unroll
        for (int p = 0; p < 8; ++p) {
            const int idx = p * 128 + tid;
            const int r = idx >> 4, q = idx & 15;
            const int w = (r << 6) + ((q ^ (r & 7)) << 2);
            Ks[w + 0] = f2tf(kv_k[p].x); Ks[w + 1] = f2tf(kv_k[p].y);
            Ks[w + 2] = f2tf(kv_k[p].z); Ks[w + 3] = f2tf(kv_k[p].w);
        }
#pragma unroll
        for (int dq = 0; dq < 8; ++dq) {
            const int d = vhalf * 32 + dq * 4;
            const float4 v = kv_v[dq];
            Vt[(d + 0) * 64 + ((((vkey >> 2) ^ ((d + 0) & 7))) << 2) + (vkey & 3)] = f2tf(v.x);
            Vt[(d + 1) * 64 + ((((vkey >> 2) ^ ((d + 1) & 7))) << 2) + (vkey & 3)] = f2tf(v.y);
            Vt[(d + 2) * 64 + ((((vkey >> 2) ^ ((d + 2) & 7))) << 2) + (vkey & 3)] = f2tf(v.z);
            Vt[(d + 3) * 64 + ((((vkey >> 2) ^ ((d + 3) & 7))) << 2) + (vkey & 3)] = f2tf(v.w);
        }
        if (tid < 64) madd[tid] = mv ? -1e30f : 0.0f;
        __syncthreads();

        const bool more = (kv0 + 64) < LL;
        // prefetch next K tile (hidden under QK mma)
        if (more) {
#pragma unroll
            for (int p = 0; p < 8; ++p) {
                const int idx = p * 128 + tid;
                const int r = idx >> 4, q = idx & 15;
                kv_k[p] = *(const float4*)(g_K + hoff + (size_t)(kv0 + 64 + r) * DM + q * 4);
            }
        }

        // S = (Q*0.125) K^T
        float s[2][8][4] = {};
#pragma unroll
        for (int ks = 0; ks < 8; ++ks) {
            const int ch = ks * 2;
            unsigned a[2][4];
#pragma unroll
            for (int mf = 0; mf < 2; ++mf) {
                const int r = warp * 32 + mf * 16 + ((lsub & 1) << 3) + lr;
                const unsigned ad =
                    qsb + (((r << 6) + (((ch + (lsub >> 1)) ^ (r & 7)) << 2)) << 2);
                ldsm4(a[mf][0], a[mf][1], a[mf][2], a[mf][3], ad);
            }
#pragma unroll
            for (int np = 0; np < 4; ++np) {
                const int r = np * 16 + ((lsub >> 1) << 3) + lr;
                const unsigned bd =
                    ksb + (((r << 6) + (((ch + (lsub & 1)) ^ (r & 7)) << 2)) << 2);
                unsigned b0, b1, b2, b3;
                ldsm4(b0, b1, b2, b3, bd);
#pragma unroll
                for (int mf = 0; mf < 2; ++mf) {
                    mma8(s[mf][np * 2 + 0], a[mf][0], a[mf][1], a[mf][2], a[mf][3], b0, b1);
                    mma8(s[mf][np * 2 + 1], a[mf][0], a[mf][1], a[mf][2], a[mf][3], b2, b3);
                }
            }
        }

        // prefetch next V/mask (hidden under softmax + PV mma)
        if (more) {
#pragma unroll
            for (int dq = 0; dq < 8; ++dq) {
                const int d = vhalf * 32 + dq * 4;
                kv_v[dq] = *(const float4*)(g_V + hoff + (size_t)(kv0 + 64 + vkey) * DM + d);
            }
            if (tid < 64) mv = mask[(size_t)b * LL + kv0 + 64 + tid];
        }

        // mask + online softmax
#pragma unroll
        for (int mf = 0; mf < 2; ++mf) {
            float rm0 = -1e30f, rm1 = -1e30f;
#pragma unroll
            for (int nf = 0; nf < 8; ++nf) {
                const float2 ma = *(const float2*)&madd[nf * 8 + 2 * tg];
                s[mf][nf][0] += ma.x; s[mf][nf][1] += ma.y;
                s[mf][nf][2] += ma.x; s[mf][nf][3] += ma.y;
                rm0 = fmaxf(rm0, fmaxf(s[mf][nf][0], s[mf][nf][1]));
                rm1 = fmaxf(rm1, fmaxf(s[mf][nf][2], s[mf][nf][3]));
            }
            rm0 = fmaxf(rm0, __shfl_xor_sync(0xffffffffu, rm0, 1));
            rm0 = fmaxf(rm0, __shfl_xor_sync(0xffffffffu, rm0, 2));
            rm1 = fmaxf(rm1, __shfl_xor_sync(0xffffffffu, rm1, 1));
            rm1 = fmaxf(rm1, __shfl_xor_sync(0xffffffffu, rm1, 2));
            const float mn0 = fmaxf(m[mf][0], rm0), mn1 = fmaxf(m[mf][1], rm1);
            const float corr0 = fexp(m[mf][0] - mn0), corr1 = fexp(m[mf][1] - mn1);
            m[mf][0] = mn0; m[mf][1] = mn1;

            float rs0 = 0.0f, rs1 = 0.0f;
            const int prow0 = warp * 32 + mf * 16 + g;
#pragma unroll
            for (int nf = 0; nf < 8; ++nf) {
                const float p0 = fexp(s[mf][nf][0] - mn0);
                const float p1 = fexp(s[mf][nf][1] - mn0);
                const float p2 = fexp(s[mf][nf][2] - mn1);
                const float p3 = fexp(s[mf][nf][3] - mn1);
                rs0 += p0 + p1; rs1 += p2 + p3;
                const int col = nf * 8 + 2 * tg;
                const int w0 = (prow0 << 6) + ((((col >> 2) ^ (prow0 & 7))) << 2) + (col & 3);
                *(uint2*)&Ps[w0] = make_uint2(f2tf(p0), f2tf(p1));
                const int prow1 = prow0 + 8;
                const int w1 = (prow1 << 6) + ((((col >> 2) ^ (prow1 & 7))) << 2) + (col & 3);
                *(uint2*)&Ps[w1] = make_uint2(f2tf(p2), f2tf(p3));
            }
            rs0 += __shfl_xor_sync(0xffffffffu, rs0, 1);
            rs0 += __shfl_xor_sync(0xffffffffu, rs0, 2);
            rs1 += __shfl_xor_sync(0xffffffffu, rs1, 1);
            rs1 += __shfl_xor_sync(0xffffffffu, rs1, 2);
            l[mf][0] = l[mf][0] * corr0 + rs0;
            l[mf][1] = l[mf][1] * corr1 + rs1;
#pragma unroll
            for (int nf = 0; nf < 8; ++nf) {
                o[mf][nf][0] *= corr0; o[mf][nf][1] *= corr0;
                o[mf][nf][2] *= corr1; o[mf][nf][3] *= corr1;
            }
        }
        __syncwarp();

        // O += P V
#pragma unroll
        for (int ks = 0; ks < 8; ++ks) {
            const int ch = ks * 2;
            unsigned a[2][4];
#pragma unroll
            for (int mf = 0; mf < 2; ++mf) {
                const int r = warp * 32 + mf * 16 + ((lsub & 1) << 3) + lr;
                const unsigned ad =
                    psb + (((r << 6) + (((ch + (lsub >> 1)) ^ (r & 7)) << 2)) << 2);
                ldsm4(a[mf][0], a[mf][1], a[mf][2], a[mf][3], ad);
            }
#pragma unroll
            for (int np = 0; np < 4; ++np) {
                const int rv = np * 16 + ((lsub >> 1) << 3) + lr;
                const unsigned bd =
                    vtb + (((rv << 6) + (((ch + (lsub & 1)) ^ (rv & 7)) << 2)) << 2);
                unsigned b0, b1, b2, b3;
                ldsm4(b0, b1, b2, b3, bd);
#pragma unroll
                for (int mf = 0; mf < 2; ++mf) {
                    mma8(o[mf][np * 2 + 0], a[mf][0], a[mf][1], a[mf][2], a[mf][3], b0, b1);
                    mma8(o[mf][np * 2 + 1], a[mf][0], a[mf][1], a[mf][2], a[mf][3], b2, b3);
                }
            }
        }
        __syncthreads();
    }

    // epilogue -> g_ctx (B, L, H*Dv)
#pragma unroll
    for (int mf = 0; mf < 2; ++mf) {
        const float inv0 = 1.0f / l[mf][0], inv1 = 1.0f / l[mf][1];
#pragma unroll
        for (int nf = 0; nf < 8; ++nf) {
            const int row = q0 + warp * 32 + mf * 16 + g;
            const int col = nf * 8 + 2 * tg;
            *(float2*)(g_ctx + hoff + (size_t)row * DM + col) =
                make_float2(o[mf][nf][0] * inv0, o[mf][nf][1] * inv0);
            *(float2*)(g_ctx + hoff + (size_t)(row + 8) * DM + col) =
                make_float2(o[mf][nf][2] * inv1, o[mf][nf][3] * inv1);
        }
    }
}

// ---------------------------------------------------------------------------
// Launch
// ---------------------------------------------------------------------------
extern "C" void kernel_launch(void* const* d_in, const int* in_sizes, int n_in,
                              void* d_out, int out_size) {
    const float* x          = (const float*)d_in[0];
    const unsigned char* mk = (const unsigned char*)d_in[1];
    const float* Wq         = (const float*)d_in[2];
    const float* Wk         = (const float*)d_in[3];
    const float* Wv         = (const float*)d_in[4];
    const float* Wo         = (const float*)d_in[5];
    float* out              = (float*)d_out;

    cudaFuncSetAttribute(qkv_gemm, cudaFuncAttributeMaxDynamicSharedMemorySize,
                         GEMM_SMEM);
    cudaFuncSetAttribute(out_gemm, cudaFuncAttributeMaxDynamicSharedMemorySize,
                         GEMM_SMEM);
    cudaFuncSetAttribute(flash_tf32, cudaFuncAttributeMaxDynamicSharedMemorySize,
                         ATT_SMEM);

    dim3 gq(DM / 128, MROWS / 256, 3);   // (8, 32, 3)
    qkv_gemm<<<gq, 256, GEMM_SMEM>>>(x, Wq, Wk, Wv);

    dim3 gf(LL / 128, BB * HH);          // (16, 64)
    flash_tf32<<<gf, 128, ATT_SMEM>>>(mk);

    dim3 go(DM / 128, MROWS / 256, 1);   // (8, 32)
    out_gemm<<<go, 256, GEMM_SMEM>>>(Wo, out);
}

// round 7
// speedup vs baseline: 3.5041x; 1.0011x over previous
#include <cuda_runtime.h>
#include <cuda_bf16.h>
#include <cstdint>

// Problem constants: B=4, L=2048, D_MODEL=1024, H=16, Dh=Dv=64
#define BB 4
#define LL 2048
#define DM 1024
#define HH 16
#define DH 64
#define MROWS (BB * LL)   // 8192

__device__ float g_Q[MROWS * DM];
__device__ float g_K[MROWS * DM];
__device__ float g_V[MROWS * DM];
__device__ float g_ctx[MROWS * DM];

// ---------------------------------------------------------------------------
// helpers
// ---------------------------------------------------------------------------
__device__ __forceinline__ unsigned f2tf(float f) {
    unsigned u;
    asm("cvt.rna.tf32.f32 %0, %1;" : "=r"(u) : "f"(f));
    return u;
}
__device__ __forceinline__ unsigned scvta(const void* p) {
    return (unsigned)__cvta_generic_to_shared(p);
}
__device__ __forceinline__ void ldsm4(unsigned& r0, unsigned& r1, unsigned& r2,
                                      unsigned& r3, unsigned a) {
    asm volatile("ldmatrix.sync.aligned.m8n8.x4.shared.b16 {%0,%1,%2,%3},[%4];"
                 : "=r"(r0), "=r"(r1), "=r"(r2), "=r"(r3) : "r"(a));
}
__device__ __forceinline__ void mma8(float* c, unsigned a0, unsigned a1,
                                     unsigned a2, unsigned a3, unsigned b0,
                                     unsigned b1) {
    asm volatile(
        "mma.sync.aligned.m16n8k8.row.col.f32.tf32.tf32.f32 "
        "{%0,%1,%2,%3},{%4,%5,%6,%7},{%8,%9},{%0,%1,%2,%3};"
        : "+f"(c[0]), "+f"(c[1]), "+f"(c[2]), "+f"(c[3])
        : "r"(a0), "r"(a1), "r"(a2), "r"(a3), "r"(b0), "r"(b1));
}
__device__ __forceinline__ float fexp(float x) {
    float y = fmaxf(x * 1.4426950408889634f, -126.0f);
    float z = y + 12582912.0f;
    int   e = __float_as_int(z) << 23;
    float f = y - (z - 12582912.0f);
    float p = fmaf(1.33336e-3f, f, 9.61813e-3f);
    p = fmaf(p, f, 5.55041e-2f);
    p = fmaf(p, f, 0.240227f);
    p = fmaf(p, f, 0.693147f);
    p = fmaf(p, f, 1.0f);
    return __int_as_float(__float_as_int(p) + e);
}

// ---------------------------------------------------------------------------
// tf32 SGEMM v3: double-buffered smem, one barrier per chunk.
// Tile 256x128, BK=32, 8 warps, warp tile 64x64.
// smem word(row,col) = row*32 + ((col/4 ^ (row&7))*4) + col%4
// buffers: As[2] (8192 words each), Bs[2] (4096 words each) = 96KB
// ---------------------------------------------------------------------------
#define GEMM_SMEM 98304

__device__ __forceinline__ void gemm_body(const float* __restrict__ A,
                                          const float* __restrict__ W,
                                          float* __restrict__ C) {
    extern __shared__ unsigned gsm[];
    // layout: As0 @0, As1 @8192, Bs0 @16384, Bs1 @20480 (words)

    const int tid = threadIdx.x, lane = tid & 31, warp = tid >> 5;
    const int wm = warp & 3, wn = warp >> 2;
    const int row0 = blockIdx.y * 256, col0 = blockIdx.x * 128;
    const int lsub = lane >> 3, lr = lane & 7;
    const int g = lane >> 2, tg = lane & 3;
    const unsigned sbase = scvta(gsm);

    int ar[8], aq[8], asw[8];
#pragma unroll
    for (int p = 0; p < 8; ++p) {
        const int i = p * 256 + tid;
        ar[p] = i >> 3; aq[p] = i & 7;
        asw[p] = (ar[p] << 5) + ((aq[p] ^ (ar[p] & 7)) << 2);
    }
    int br[4], bq[4], bsw[4];
#pragma unroll
    for (int p = 0; p < 4; ++p) {
        const int i = p * 256 + tid;
        br[p] = i >> 3; bq[p] = i & 7;
        bsw[p] = (br[p] << 5) + ((bq[p] ^ (br[p] & 7)) << 2);
    }

    float acc[4][8][4] = {};
    float4 av[8], bv[4];

    // prologue: chunk 0 -> regs -> buf0
#pragma unroll
    for (int p = 0; p < 8; ++p)
        av[p] = *(const float4*)(A + (size_t)(row0 + ar[p]) * DM + aq[p] * 4);
#pragma unroll
    for (int p = 0; p < 4; ++p)
        bv[p] = *(const float4*)(W + (size_t)(col0 + br[p]) * DM + bq[p] * 4);
#pragma unroll
    for (int p = 0; p < 8; ++p) {
        uint4 u;
        u.x = f2tf(av[p].x); u.y = f2tf(av[p].y);
        u.z = f2tf(av[p].z); u.w = f2tf(av[p].w);
        *(uint4*)(gsm + asw[p]) = u;
    }
#pragma unroll
    for (int p = 0; p < 4; ++p) {
        uint4 u;
        u.x = f2tf(bv[p].x); u.y = f2tf(bv[p].y);
        u.z = f2tf(bv[p].z); u.w = f2tf(bv[p].w);
        *(uint4*)(gsm + 16384 + bsw[p]) = u;
    }
    __syncthreads();

    for (int c = 0; c < 32; ++c) {
        const int cur = c & 1, nxt = cur ^ 1;
        const bool more = c < 31;
        // prefetch next chunk into regs (hidden under mma below)
        if (more) {
            const int kk = (c + 1) * 32;
#pragma unroll
            for (int p = 0; p < 8; ++p)
                av[p] = *(const float4*)(A + (size_t)(row0 + ar[p]) * DM + kk + aq[p] * 4);
#pragma unroll
            for (int p = 0; p < 4; ++p)
                bv[p] = *(const float4*)(W + (size_t)(col0 + br[p]) * DM + kk + bq[p] * 4);
        }

        const unsigned asb = sbase + cur * 32768u;
        const unsigned bsb = sbase + 65536u + cur * 16384u;
#pragma unroll
        for (int ks = 0; ks < 4; ++ks) {
            const int ch = ks * 2;
            unsigned a[4][4], b[4][4];
#pragma unroll
            for (int mf = 0; mf < 4; ++mf) {
                const int r = wm * 64 + mf * 16 + ((lsub & 1) << 3) + lr;
                const unsigned ad =
                    asb + (((r << 5) + (((ch + (lsub >> 1)) ^ (r & 7)) << 2)) << 2);
                ldsm4(a[mf][0], a[mf][1], a[mf][2], a[mf][3], ad);
            }
#pragma unroll
            for (int np = 0; np < 4; ++np) {
                const int r = wn * 64 + np * 16 + ((lsub >> 1) << 3) + lr;
                const unsigned bd =
                    bsb + (((r << 5) + (((ch + (lsub & 1)) ^ (r & 7)) << 2)) << 2);
                ldsm4(b[np][0], b[np][1], b[np][2], b[np][3], bd);
            }
#pragma unroll
            for (int mf = 0; mf < 4; ++mf)
#pragma unroll
                for (int np = 0; np < 4; ++np) {
                    mma8(acc[mf][np * 2 + 0], a[mf][0], a[mf][1], a[mf][2], a[mf][3],
                         b[np][0], b[np][1]);
                    mma8(acc[mf][np * 2 + 1], a[mf][0], a[mf][1], a[mf][2], a[mf][3],
                         b[np][2], b[np][3]);
                }
        }

        // store next chunk into the other buffer (overlaps tail of mma)
        if (more) {
            unsigned* Asn = gsm + nxt * 8192;
            unsigned* Bsn = gsm + 16384 + nxt * 4096;
#pragma unroll
            for (int p = 0; p < 8; ++p) {
                uint4 u;
                u.x = f2tf(av[p].x); u.y = f2tf(av[p].y);
                u.z = f2tf(av[p].z); u.w = f2tf(av[p].w);
                *(uint4*)(Asn + asw[p]) = u;
            }
#pragma unroll
            for (int p = 0; p < 4; ++p) {
                uint4 u;
                u.x = f2tf(bv[p].x); u.y = f2tf(bv[p].y);
                u.z = f2tf(bv[p].z); u.w = f2tf(bv[p].w);
                *(uint4*)(Bsn + bsw[p]) = u;
            }
        }
        __syncthreads();
    }

#pragma unroll
    for (int mf = 0; mf < 4; ++mf)
#pragma unroll
        for (int nf = 0; nf < 8; ++nf) {
            const int row = row0 + wm * 64 + mf * 16 + g;
            const int col = col0 + wn * 64 + nf * 8 + 2 * tg;
            *(float2*)(C + (size_t)row * DM + col) =
                make_float2(acc[mf][nf][0], acc[mf][nf][1]);
            *(float2*)(C + (size_t)(row + 8) * DM + col) =
                make_float2(acc[mf][nf][2], acc[mf][nf][3]);
        }
}

__global__ void __launch_bounds__(256, 1)
qkv_gemm(const float* __restrict__ x, const float* __restrict__ Wq,
         const float* __restrict__ Wk, const float* __restrict__ Wv) {
    const float* W = (blockIdx.z == 0) ? Wq : (blockIdx.z == 1) ? Wk : Wv;
    float* C = (blockIdx.z == 0) ? g_Q : (blockIdx.z == 1) ? g_K : g_V;
    gemm_body(x, W, C);
}

__global__ void __launch_bounds__(256, 1)
out_gemm(const float* __restrict__ Wo, float* __restrict__ out) {
    gemm_body(g_ctx, Wo, out);
}

// ---------------------------------------------------------------------------
// Flash attention v3: 256 threads (8 warps), Br=256, Bc=64, 32 q-rows/warp.
// K and Vt double-buffered -> ONE __syncthreads per kv-tile; stores for t+1
// issue right after QK(t). smem 192KB, 1 CTA/SM (2 warps/SMSP unchanged).
// word(row,col) = row*64 + ((col/4 ^ (row&7))*4) + col%4
// layout (words): Qs @0 (16384), Ps @16384 (16384), K0 @32768, K1 @36864,
//                 V0 @40960, V1 @45056, madd2 @49152 (2x64 floats)
// ---------------------------------------------------------------------------
#define ATT_SMEM (49152 * 4 + 2 * 64 * 4)

__global__ void __launch_bounds__(256, 1)
flash_tf32(const unsigned char* __restrict__ mask) {
    extern __shared__ unsigned sm[];
    unsigned* Qs = sm;
    unsigned* Ps = sm + 16384;
    float* madd2 = (float*)(sm + 49152);

    const int tid = threadIdx.x, lane = tid & 31, warp = tid >> 5;
    const int lsub = lane >> 3, lr = lane & 7;
    const int g = lane >> 2, tg = lane & 3;
    const int bh = blockIdx.y, b = bh >> 4, h = bh & 15;
    const int q0 = blockIdx.x * 256;
    const size_t hoff = (size_t)b * LL * DM + (size_t)h * DH;
    const unsigned qsb = scvta(Qs), psb = scvta(Ps);
    const unsigned kb0 = scvta(sm + 32768), vb0 = scvta(sm + 40960);

    // K/V load geometry: K 4 float4/thread, V 4 float4/thread
    const int vkey = tid & 63, vquar = tid >> 6;   // quarter owns d 16*q..16*q+15

    float4 kv_k[4], kv_v[4];
    unsigned char mv = 0;

    // prologue: Q tile (scaled) -> smem
#pragma unroll
    for (int p = 0; p < 16; ++p) {
        const int idx = p * 256 + tid;
        const int r = idx >> 4, q = idx & 15;
        const float4 v = *(const float4*)(g_Q + hoff + (size_t)(q0 + r) * DM + q * 4);
        const int w = (r << 6) + ((q ^ (r & 7)) << 2);
        Qs[w + 0] = f2tf(v.x * 0.125f); Qs[w + 1] = f2tf(v.y * 0.125f);
        Qs[w + 2] = f2tf(v.z * 0.125f); Qs[w + 3] = f2tf(v.w * 0.125f);
    }
    // first K/V tile -> regs -> buf0
#pragma unroll
    for (int p = 0; p < 4; ++p) {
        const int idx = p * 256 + tid;
        const int r = idx >> 4, q = idx & 15;
        kv_k[p] = *(const float4*)(g_K + hoff + (size_t)r * DM + q * 4);
    }
#pragma unroll
    for (int dq = 0; dq < 4; ++dq) {
        const int d = vquar * 16 + dq * 4;
        kv_v[dq] = *(const float4*)(g_V + hoff + (size_t)vkey * DM + d);
    }
    if (tid < 64) mv = mask[(size_t)b * LL + tid];
    {
        unsigned* K0 = sm + 32768;
        unsigned* V0 = sm + 40960;
#pragma unroll
        for (int p = 0; p < 4; ++p) {
            const int idx = p * 256 + tid;
            const int r = idx >> 4, q = idx & 15;
            const int w = (r << 6) + ((q ^ (r & 7)) << 2);
            K0[w + 0] = f2tf(kv_k[p].x); K0[w + 1] = f2tf(kv_k[p].y);
            K0[w + 2] = f2tf(kv_k[p].z); K0[w + 3] = f2tf(kv_k[p].w);
        }
#pragma unroll
        for (int dq = 0; dq < 4; ++dq) {
            const int d = vquar * 16 + dq * 4;
            const float4 v = kv_v[dq];
            V0[(d + 0) * 64 + ((((vkey >> 2) ^ ((d + 0) & 7))) << 2) + (vkey & 3)] = f2tf(v.x);
            V0[(d + 1) * 64 + ((((vkey >> 2) ^ ((d + 1) & 7))) << 2) + (vkey & 3)] = f2tf(v.y);
            V0[(d + 2) * 64 + ((((vkey >> 2) ^ ((d + 2) & 7))) << 2) + (vkey & 3)] = f2tf(v.z);
            V0[(d + 3) * 64 + ((((vkey >> 2) ^ ((d + 3) & 7))) << 2) + (vkey & 3)] = f2tf(v.w);
        }
        if (tid < 64) madd2[tid] = mv ? -1e30f : 0.0f;
    }
    __syncthreads();

    float m[2][2], l[2][2];
#pragma unroll
    for (int mf = 0; mf < 2; ++mf) { m[mf][0] = m[mf][1] = -1e30f; l[mf][0] = l[mf][1] = 0.0f; }
    float o[2][8][4] = {};

    for (int t = 0; t < 32; ++t) {
        const int cur = t & 1, nxt = cur ^ 1;
        const bool more = t < 31;
        const int kv0 = t * 64;
        const unsigned ksb = kb0 + cur * 16384u;
        const unsigned vtb = vb0 + cur * 16384u;
        const float* maddc = madd2 + cur * 64;

        // prefetch next K/V/mask into regs
        if (more) {
#pragma unroll
            for (int p = 0; p < 4; ++p) {
                const int idx = p * 256 + tid;
                const int r = idx >> 4, q = idx & 15;
                kv_k[p] = *(const float4*)(g_K + hoff + (size_t)(kv0 + 64 + r) * DM + q * 4);
            }
#pragma unroll
            for (int dq = 0; dq < 4; ++dq) {
                const int d = vquar * 16 + dq * 4;
                kv_v[dq] = *(const float4*)(g_V + hoff + (size_t)(kv0 + 64 + vkey) * DM + d);
            }
            if (tid < 64) mv = mask[(size_t)b * LL + kv0 + 64 + tid];
        }

        // S = (Q*0.125) K^T
        float s[2][8][4] = {};
#pragma unroll
        for (int ks = 0; ks < 8; ++ks) {
            const int ch = ks * 2;
            unsigned a[2][4];
#pragma unroll
            for (int mf = 0; mf < 2; ++mf) {
                const int r = warp * 32 + mf * 16 + ((lsub & 1) << 3) + lr;
                const unsigned ad =
                    qsb + (((r << 6) + (((ch + (lsub >> 1)) ^ (r & 7)) << 2)) << 2);
                ldsm4(a[mf][0], a[mf][1], a[mf][2], a[mf][3], ad);
            }
#pragma unroll
            for (int np = 0; np < 4; ++np) {
                const int r = np * 16 + ((lsub >> 1) << 3) + lr;
                const unsigned bd =
                    ksb + (((r << 6) + (((ch + (lsub & 1)) ^ (r & 7)) << 2)) << 2);
                unsigned b0, b1, b2, b3;
                ldsm4(b0, b1, b2, b3, bd);
#pragma unroll
                for (int mf = 0; mf < 2; ++mf) {
                    mma8(s[mf][np * 2 + 0], a[mf][0], a[mf][1], a[mf][2], a[mf][3], b0, b1);
                    mma8(s[mf][np * 2 + 1], a[mf][0], a[mf][1], a[mf][2], a[mf][3], b2, b3);
                }
            }
        }

        // store next K/V/mask into other buffer (safe: t-1 readers done at last sync)
        if (more) {
            unsigned* Kn = sm + 32768 + nxt * 4096;
            unsigned* Vn = sm + 40960 + nxt * 4096;
#pragma unroll
            for (int p = 0; p < 4; ++p) {
                const int idx = p * 256 + tid;
                const int r = idx >> 4, q = idx & 15;
                const int w = (r << 6) + ((q ^ (r & 7)) << 2);
                Kn[w + 0] = f2tf(kv_k[p].x); Kn[w + 1] = f2tf(kv_k[p].y);
                Kn[w + 2] = f2tf(kv_k[p].z); Kn[w + 3] = f2tf(kv_k[p].w);
            }
#pragma unroll
            for (int dq = 0; dq < 4; ++dq) {
                const int d = vquar * 16 + dq * 4;
                const float4 v = kv_v[dq];
                Vn[(d + 0) * 64 + ((((vkey >> 2) ^ ((d + 0) & 7))) << 2) + (vkey & 3)] = f2tf(v.x);
                Vn[(d + 1) * 64 + ((((vkey >> 2) ^ ((d + 1) & 7))) << 2) + (vkey & 3)] = f2tf(v.y);
                Vn[(d + 2) * 64 + ((((vkey >> 2) ^ ((d + 2) & 7))) << 2) + (vkey & 3)] = f2tf(v.z);
                Vn[(d + 3) * 64 + ((((vkey >> 2) ^ ((d + 3) & 7))) << 2) + (vkey & 3)] = f2tf(v.w);
            }
            if (tid < 64) madd2[nxt * 64 + tid] = mv ? -1e30f : 0.0f;
        }

        // mask + online softmax
#pragma unroll
        for (int mf = 0; mf < 2; ++mf) {
            float rm0 = -1e30f, rm1 = -1e30f;
#pragma unroll
            for (int nf = 0; nf < 8; ++nf) {
                const float2 ma = *(const float2*)&maddc[nf * 8 + 2 * tg];
                s[mf][nf][0] += ma.x; s[mf][nf][1] += ma.y;
                s[mf][nf][2] += ma.x; s[mf][nf][3] += ma.y;
                rm0 = fmaxf(rm0, fmaxf(s[mf][nf][0], s[mf][nf][1]));
                rm1 = fmaxf(rm1, fmaxf(s[mf][nf][2], s[mf][nf][3]));
            }
            rm0 = fmaxf(rm0, __shfl_xor_sync(0xffffffffu, rm0, 1));
            rm0 = fmaxf(rm0, __shfl_xor_sync(0xffffffffu, rm0, 2));
            rm1 = fmaxf(rm1, __shfl_xor_sync(0xffffffffu, rm1, 1));
            rm1 = fmaxf(rm1, __shfl_xor_sync(0xffffffffu, rm1, 2));
            const float mn0 = fmaxf(m[mf][0], rm0), mn1 = fmaxf(m[mf][1], rm1);
            const float corr0 = fexp(m[mf][0] - mn0), corr1 = fexp(m[mf][1] - mn1);
            m[mf][0] = mn0; m[mf][1] = mn1;

            float rs0 = 0.0f, rs1 = 0.0f;
            const int prow0 = warp * 32 + mf * 16 + g;
#pragma unroll
            for (int nf = 0; nf < 8; ++nf) {
                const float p0 = fexp(s[mf][nf][0] - mn0);
                const float p1 = fexp(s[mf][nf][1] - mn0);
                const float p2 = fexp(s[mf][nf][2] - mn1);
                const float p3 = fexp(s[mf][nf][3] - mn1);
                rs0 += p0 + p1; rs1 += p2 + p3;
                const int col = nf * 8 + 2 * tg;
                const int w0 = (prow0 << 6) + ((((col >> 2) ^ (prow0 & 7))) << 2) + (col & 3);
                *(uint2*)&Ps[w0] = make_uint2(f2tf(p0), f2tf(p1));
                const int prow1 = prow0 + 8;
                const int w1 = (prow1 << 6) + ((((col >> 2) ^ (prow1 & 7))) << 2) + (col & 3);
                *(uint2*)&Ps[w1] = make_uint2(f2tf(p2), f2tf(p3));
            }
            rs0 += __shfl_xor_sync(0xffffffffu, rs0, 1);
            rs0 += __shfl_xor_sync(0xffffffffu, rs0, 2);
            rs1 += __shfl_xor_sync(0xffffffffu, rs1, 1);
            rs1 += __shfl_xor_sync(0xffffffffu, rs1, 2);
            l[mf][0] = l[mf][0] * corr0 + rs0;
            l[mf][1] = l[mf][1] * corr1 + rs1;
#pragma unroll
            for (int nf = 0; nf < 8; ++nf) {
                o[mf][nf][0] *= corr0; o[mf][nf][1] *= corr0;
                o[mf][nf][2] *= corr1; o[mf][nf][3] *= corr1;
            }
        }
        __syncwarp();

        // O += P V
#pragma unroll
        for (int ks = 0; ks < 8; ++ks) {
            const int ch = ks * 2;
            unsigned a[2][4];
#pragma unroll
            for (int mf = 0; mf < 2; ++mf) {
                const int r = warp * 32 + mf * 16 + ((lsub & 1) << 3) + lr;
                const unsigned ad =
                    psb + (((r << 6) + (((ch + (lsub >> 1)) ^ (r & 7)) << 2)) << 2);
                ldsm4(a[mf][0], a[mf][1], a[mf][2], a[mf][3], ad);
            }
#pragma unroll
            for (int np = 0; np < 4; ++np) {
                const int rv = np * 16 + ((lsub >> 1) << 3) + lr;
                const unsigned bd =
                    vtb + (((rv << 6) + (((ch + (lsub & 1)) ^ (rv & 7)) << 2)) << 2);
                unsigned b0, b1, b2, b3;
                ldsm4(b0, b1, b2, b3, bd);
#pragma unroll
                for (int mf = 0; mf < 2; ++mf) {
                    mma8(o[mf][np * 2 + 0], a[mf][0], a[mf][1], a[mf][2], a[mf][3], b0, b1);
                    mma8(o[mf][np * 2 + 1], a[mf][0], a[mf][1], a[mf][2], a[mf][3], b2, b3);
                }
            }
        }
        __syncthreads();   // single barrier per tile
    }

    // epilogue -> g_ctx (B, L, H*Dv)
#pragma unroll
    for (int mf = 0; mf < 2; ++mf) {
        const float inv0 = 1.0f / l[mf][0], inv1 = 1.0f / l[mf][1];
#pragma unroll
        for (int nf = 0; nf < 8; ++nf) {
            const int row = q0 + warp * 32 + mf * 16 + g;
            const int col = nf * 8 + 2 * tg;
            *(float2*)(g_ctx + hoff + (size_t)row * DM + col) =
                make_float2(o[mf][nf][0] * inv0, o[mf][nf][1] * inv0);
            *(float2*)(g_ctx + hoff + (size_t)(row + 8) * DM + col) =
                make_float2(o[mf][nf][2] * inv1, o[mf][nf][3] * inv1);
        }
    }
}

// ---------------------------------------------------------------------------
// Launch
// ---------------------------------------------------------------------------
extern "C" void kernel_launch(void* const* d_in, const int* in_sizes, int n_in,
                              void* d_out, int out_size) {
    const float* x          = (const float*)d_in[0];
    const unsigned char* mk = (const unsigned char*)d_in[1];
    const float* Wq         = (const float*)d_in[2];
    const float* Wk         = (const float*)d_in[3];
    const float* Wv         = (const float*)d_in[4];
    const float* Wo         = (const float*)d_in[5];
    float* out              = (float*)d_out;

    cudaFuncSetAttribute(qkv_gemm, cudaFuncAttributeMaxDynamicSharedMemorySize,
                         GEMM_SMEM);
    cudaFuncSetAttribute(out_gemm, cudaFuncAttributeMaxDynamicSharedMemorySize,
                         GEMM_SMEM);
    cudaFuncSetAttribute(flash_tf32, cudaFuncAttributeMaxDynamicSharedMemorySize,
                         ATT_SMEM);

    dim3 gq(DM / 128, MROWS / 256, 3);   // (8, 32, 3)
    qkv_gemm<<<gq, 256, GEMM_SMEM>>>(x, Wq, Wk, Wv);

    dim3 gf(LL / 256, BB * HH);          // (8, 64)
    flash_tf32<<<gf, 256, ATT_SMEM>>>(mk);

    dim3 go(DM / 128, MROWS / 256, 1);   // (8, 32)
    out_gemm<<<go, 256, GEMM_SMEM>>>(Wo, out);
}